// round 12
// baseline (speedup 1.0000x reference)
#include <cuda_runtime.h>
#include <cuda_fp16.h>
#include <math.h>
#include <stdint.h>

// ================= constants =================
namespace {
constexpr int Cc = 768, NH = 12, HD = 64, WS = 14, MLP = 3072;
constexpr int NWIN = 200, NTOK = 196;
constexpr int M2 = 8 * 64 * 64;   // 32768 (image tokens, compact M)
constexpr float EPS = 1e-6f;

constexpr int BM = 128, BN = 128, BK = 64;
constexpr int ROWB = 144;                // 64 fp16 = 128B + 16B pad
constexpr int ARR = BM * ROWB;           // 18432
constexpr int STAGE = 2 * ARR;           // 36864 (A, B)
constexpr int NSTG = 3;
constexpr int DYN_SMEM = NSTG * STAGE;   // 110592 (3 stages, 2 CTA/SM)

// attention smem layout (bytes) — single CTA per (win,head), 13 warps
constexpr int QEROW = 208;                      // 96 halves + 8 pad
constexpr int QE_OFF = 0;                       // 224 x 208
constexpr int KE_OFF = 224 * QEROW;             // 46592
constexpr int V_OFF = KE_OFF + 224 * QEROW;     // 93184 (224 x 144)
constexpr int R_OFF = V_OFF + 224 * 144;        // 125440 (64 x 144)
constexpr int ATTN_SMEM = R_OFF + 64 * 144;     // 134656
constexpr int ATH = 416;                        // 13 warps
}

// ================= device scratch =================
__device__ __align__(16) __half g_xln[(size_t)M2 * Cc];
__device__ __align__(16) __half g_q[(size_t)NWIN * NH * NTOK * HD];
__device__ __align__(16) __half g_k[(size_t)NWIN * NH * NTOK * HD];
__device__ __align__(16) __half g_v[(size_t)NWIN * NH * NTOK * HD];
__device__ __align__(16) __half g_attn[(size_t)M2 * Cc];   // image layout
__device__ __align__(16) float g_h[(size_t)M2 * Cc];
__device__ __align__(16) __half g_x2[(size_t)M2 * Cc];
__device__ __align__(16) __half g_m1[(size_t)M2 * MLP];
__device__ __align__(16) __half g_wq[(size_t)3 * Cc * Cc];
__device__ __align__(16) __half g_wp[(size_t)Cc * Cc];
__device__ __align__(16) __half g_w1[(size_t)MLP * Cc];
__device__ __align__(16) __half g_w2[(size_t)Cc * MLP];

// ================= helpers =================
__device__ __forceinline__ uint32_t s2u(const void* p) {
  uint32_t a;
  asm("{ .reg .u64 t; cvta.to.shared.u64 t, %1; cvt.u32.u64 %0, t; }"
      : "=r"(a) : "l"(p));
  return a;
}
__device__ __forceinline__ void cpa16(uint32_t dst, const void* src, uint32_t sz) {
  asm volatile("cp.async.cg.shared.global [%0], [%1], 16, %2;"
               :: "r"(dst), "l"(src), "r"(sz) : "memory");
}
#define CP_COMMIT() asm volatile("cp.async.commit_group;" ::: "memory")
#define CP_WAIT1() asm volatile("cp.async.wait_group 1;" ::: "memory")

__device__ __forceinline__ void ldsm_x4(uint32_t* r, uint32_t a) {
  asm volatile("ldmatrix.sync.aligned.m8n8.x4.shared.b16 {%0,%1,%2,%3}, [%4];"
               : "=r"(r[0]), "=r"(r[1]), "=r"(r[2]), "=r"(r[3]) : "r"(a));
}
__device__ __forceinline__ void ldsm_x4_t(uint32_t* r, uint32_t a) {
  asm volatile("ldmatrix.sync.aligned.m8n8.x4.trans.shared.b16 {%0,%1,%2,%3}, [%4];"
               : "=r"(r[0]), "=r"(r[1]), "=r"(r[2]), "=r"(r[3]) : "r"(a));
}
__device__ __forceinline__ void mma_fp16(float* d, const uint32_t* a,
                                         const uint32_t* b) {
  asm volatile(
      "mma.sync.aligned.m16n8k16.row.col.f32.f16.f16.f32 "
      "{%0,%1,%2,%3},{%4,%5,%6,%7},{%8,%9},{%0,%1,%2,%3};"
      : "+f"(d[0]), "+f"(d[1]), "+f"(d[2]), "+f"(d[3])
      : "r"(a[0]), "r"(a[1]), "r"(a[2]), "r"(a[3]), "r"(b[0]), "r"(b[1]));
}
__device__ __forceinline__ float expf_fast(float x) {
  float y = fmaxf(x * 1.4426950408889634f, -126.f);
  float t = y + 12582912.f;
  int i = __float_as_int(t) - 0x4B400000;
  float f = y - (t - 12582912.f);
  float p = 0.0013333558f;
  p = fmaf(p, f, 0.0096181291f);
  p = fmaf(p, f, 0.0555041087f);
  p = fmaf(p, f, 0.2402265070f);
  p = fmaf(p, f, 0.6931471806f);
  p = fmaf(p, f, 1.0f);
  return __int_as_float(__float_as_int(p) + (i << 23));
}
__device__ __forceinline__ float rcp_fast(float d) {
  float r = __int_as_float(0x7EF311C3 - __float_as_int(d));
  r = r * fmaf(-d, r, 2.f);
  r = r * fmaf(-d, r, 2.f);
  r = r * fmaf(-d, r, 2.f);
  return r;
}
__device__ __forceinline__ float gelu_f(float x) {
  float z = fabsf(x) * 0.70710678118654752f;
  float t = rcp_fast(fmaf(0.3275911f, z, 1.f));
  float p = 1.061405429f;
  p = fmaf(p, t, -1.453152027f);
  p = fmaf(p, t, 1.421413741f);
  p = fmaf(p, t, -0.284496736f);
  p = fmaf(p, t, 0.254829592f);
  p = p * t;
  float erfz = fmaf(-p, expf_fast(-z * z), 1.f);
  float s = (x >= 0.f) ? erfz : -erfz;
  return 0.5f * x * (1.f + s);
}

// ============ merged weight transpose (fp32 -> fp16 [N][K]) ============
__global__ __launch_bounds__(256) void k_wsplit_all(const float* __restrict__ w0,
                                                    const float* __restrict__ w1,
                                                    const float* __restrict__ w2,
                                                    const float* __restrict__ w3) {
  int b = blockIdx.x;
  const float* Wsrc;
  __half* T;
  int K, N, nx, ky;
  if (b < 1728) { Wsrc = w0; T = g_wq; K = Cc; N = 3 * Cc; nx = b % 72; ky = b / 72; }
  else if (b < 2304) { b -= 1728; Wsrc = w1; T = g_wp; K = Cc; N = Cc; nx = b % 24; ky = b / 24; }
  else if (b < 4608) { b -= 2304; Wsrc = w2; T = g_w1; K = Cc; N = MLP; nx = b % 96; ky = b / 96; }
  else { b -= 4608; Wsrc = w3; T = g_w2; K = MLP; N = Cc; nx = b % 24; ky = b / 24; }
  __shared__ float t[32][33];
  int n0 = nx * 32, k0 = ky * 32;
  int tx = threadIdx.x & 31, ty = threadIdx.x >> 5;
  for (int r = ty; r < 32; r += 8)
    t[r][tx] = Wsrc[(size_t)(k0 + r) * N + n0 + tx];
  __syncthreads();
  for (int r = ty; r < 32; r += 8)
    T[(size_t)(n0 + r) * K + k0 + tx] = __float2half(t[tx][r]);
}

// === fill padded q/k/v slots with bias (padded LN rows are zero rows) ===
__global__ __launch_bounds__(256) void k_fillkv(const float* __restrict__ qkvb) {
  int win = blockIdx.x;
  int wr = win % 25;
  int wh = wr / 5, ww = wr % 5;
  if (wh != 4 && ww != 4) return;
  for (int idx = threadIdx.x; idx < NTOK * NH; idx += 256) {
    int tok = idx / NH, head = idx - (idx / NH) * NH;
    int i = tok / WS, j = tok - i * WS;
    int h = wh * WS + i, w = ww * WS + j;
    if (h < 64 && w < 64) continue;
    size_t row = (((size_t)(win * NH + head)) * NTOK + tok) * HD;
    const float* qb = qkvb + head * HD;
    const float* kb = qkvb + Cc + head * HD;
    const float* vb = qkvb + 2 * Cc + head * HD;
#pragma unroll
    for (int d = 0; d < HD; d += 2) {
      __half2 qq = __floats2half2_rn(qb[d], qb[d + 1]);
      __half2 kk = __floats2half2_rn(kb[d], kb[d + 1]);
      __half2 vv = __floats2half2_rn(vb[d], vb[d + 1]);
      *(uint32_t*)(g_q + row + d) = *reinterpret_cast<uint32_t*>(&qq);
      *(uint32_t*)(g_k + row + d) = *reinterpret_cast<uint32_t*>(&kk);
      *(uint32_t*)(g_v + row + d) = *reinterpret_cast<uint32_t*>(&vv);
    }
  }
}

// ================= layernorm (fp16 out, image layout) =================
__device__ __forceinline__ void ln_compute(const float* __restrict__ xr,
                                           const float* __restrict__ g,
                                           const float* __restrict__ bsh,
                                           __half* __restrict__ o) {
  float vals[3];
  float s = 0.f, s2 = 0.f;
#pragma unroll
  for (int t = 0; t < 3; t++) {
    float v = xr[threadIdx.x + t * 256];
    vals[t] = v; s += v; s2 += v * v;
  }
#pragma unroll
  for (int off = 16; off > 0; off >>= 1) {
    s += __shfl_down_sync(0xffffffffu, s, off);
    s2 += __shfl_down_sync(0xffffffffu, s2, off);
  }
  __shared__ float rs[8], rq[8];
  __shared__ float s_mu, s_inv;
  int lane = threadIdx.x & 31, warp = threadIdx.x >> 5;
  if (lane == 0) { rs[warp] = s; rq[warp] = s2; }
  __syncthreads();
  if (threadIdx.x == 0) {
    float a = 0.f, b2 = 0.f;
#pragma unroll
    for (int i = 0; i < 8; i++) { a += rs[i]; b2 += rq[i]; }
    float mu = a * (1.f / 768.f);
    float var = b2 * (1.f / 768.f) - mu * mu;
    s_mu = mu; s_inv = rsqrtf(var + EPS);
  }
  __syncthreads();
  float mu = s_mu, inv = s_inv;
#pragma unroll
  for (int t = 0; t < 3; t++) {
    int c = threadIdx.x + t * 256;
    o[c] = __float2half((vals[t] - mu) * inv * g[c] + bsh[c]);
  }
}

__global__ __launch_bounds__(256) void k_ln1(const float* __restrict__ x,
                                             const float* __restrict__ g,
                                             const float* __restrict__ b) {
  int m = blockIdx.x;
  ln_compute(x + (size_t)m * Cc, g, b, g_xln + (size_t)m * Cc);
}

__global__ __launch_bounds__(256) void k_ln2(const float* __restrict__ g,
                                             const float* __restrict__ b) {
  int m = blockIdx.x;
  ln_compute(g_h + (size_t)m * Cc, g, b, g_x2 + (size_t)m * Cc);
}

// ============ fp16 mma.sync GEMM (128x128, 3-stage, 2 CTA/SM) ============
enum { EPI_QKV = 0, EPI_PROJ = 1, EPI_LIN1 = 2, EPI_LIN2 = 3 };

template <int EPI>
__global__ __launch_bounds__(256, 2) void k_gemm(const float* __restrict__ bias,
                                                 const float* __restrict__ extra,
                                                 float* __restrict__ outp,
                                                 int M, int N, int K) {
  extern __shared__ __align__(128) char dsm[];
  const __half *A_g, *B_g;
  if (EPI == EPI_QKV) { A_g = g_xln; B_g = g_wq; }
  else if (EPI == EPI_PROJ) { A_g = g_attn; B_g = g_wp; }
  else if (EPI == EPI_LIN1) { A_g = g_x2; B_g = g_w1; }
  else { A_g = g_m1; B_g = g_w2; }

  const int tid = threadIdx.x;
  const int wid = tid >> 5, lane = tid & 31;
  const int wm = wid >> 2, wn = wid & 3;
  const int row0 = blockIdx.y * BM, col0 = blockIdx.x * BN;
  const uint32_t smb = s2u(dsm);
  const int nch = K / BK;

  const int lr = tid >> 3, lc16 = tid & 7;

  auto load_stage = [&](int c) {
    if (c >= nch) return;
    uint32_t sb = smb + (c % NSTG) * STAGE;
    int k0 = c * BK;
#pragma unroll
    for (int i = 0; i < 4; i++) {
      int r = lr + i * 32;
      uint32_t doff = r * ROWB + lc16 * 16;
      cpa16(sb + doff, A_g + (size_t)(row0 + r) * K + k0 + lc16 * 8, 16u);
      cpa16(sb + ARR + doff, B_g + (size_t)(col0 + r) * K + k0 + lc16 * 8, 16u);
    }
  };

  float acc[4][4][4];
#pragma unroll
  for (int i = 0; i < 4; i++)
#pragma unroll
    for (int j = 0; j < 4; j++)
#pragma unroll
      for (int q = 0; q < 4; q++) acc[i][j][q] = 0.f;

  load_stage(0); CP_COMMIT();
  load_stage(1); CP_COMMIT();

  const int arow = lane & 15, ahalf = lane >> 4;
  const int bl8 = lane & 7;
  const int bmat = lane >> 3;
  const int bnt_off = (bmat >> 1) * 8;
  const int bhalf = bmat & 1;

  for (int c = 0; c < nch; c++) {
    CP_WAIT1();
    __syncthreads();
    // issue next-next stage loads FIRST: gives them the whole chunk of
    // compute below to land (buffer (c+2)%NSTG == (c-1)%NSTG, protected
    // by the barrier above).
    load_stage(c + 2); CP_COMMIT();
    uint32_t sb = smb + (c % NSTG) * STAGE;
#pragma unroll
    for (int ks = 0; ks < 4; ks++) {
      uint32_t ah[4][4], bq[2][4];
#pragma unroll
      for (int mt = 0; mt < 4; mt++)
        ldsm_x4(ah[mt],
                sb + (wm * 64 + mt * 16 + arow) * ROWB + ks * 32 + ahalf * 16);
#pragma unroll
      for (int np = 0; np < 2; np++)
        ldsm_x4(bq[np], sb + ARR +
                            (wn * 32 + np * 16 + bnt_off + bl8) * ROWB +
                            ks * 32 + bhalf * 16);
#pragma unroll
      for (int mt = 0; mt < 4; mt++)
#pragma unroll
        for (int nt = 0; nt < 4; nt++)
          mma_fp16(acc[mt][nt], ah[mt], &bq[nt >> 1][(nt & 1) * 2]);
    }
  }

  const int er = lane >> 2, ec = (lane & 3) * 2;
#pragma unroll
  for (int mt = 0; mt < 4; mt++) {
#pragma unroll
    for (int h = 0; h < 2; h++) {
      int m = row0 + wm * 64 + mt * 16 + er + h * 8;
#pragma unroll
      for (int nt = 0; nt < 4; nt++) {
        int n = col0 + wn * 32 + nt * 8 + ec;
        float v0 = acc[mt][nt][2 * h] + bias[n];
        float v1 = acc[mt][nt][2 * h + 1] + bias[n + 1];

        if (EPI == EPI_QKV) {
          int b = m >> 12;
          int rem = m & 4095;
          int hh = rem >> 6, ww2 = rem & 63;
          int wh = (hh * 293) >> 12, ii = hh - wh * WS;
          int wwi = (ww2 * 293) >> 12, jj = ww2 - wwi * WS;
          int win = b * 25 + wh * 5 + wwi;
          int tok = ii * WS + jj;
          int part = n / Cc, cin = n - part * Cc;
          int head = cin >> 6, d = cin & 63;
          __half* dst = (part == 0 ? g_q : part == 1 ? g_k : g_v) +
                        (((size_t)(win * NH + head)) * NTOK + tok) * HD + d;
          __half2 p = __floats2half2_rn(v0, v1);
          *(uint32_t*)dst = *reinterpret_cast<uint32_t*>(&p);
        } else if (EPI == EPI_PROJ) {
          size_t o = (size_t)m * Cc + n;
          float2 r2 = *(const float2*)(extra + o);
          *(float2*)(g_h + o) = make_float2(r2.x + v0, r2.y + v1);
        } else if (EPI == EPI_LIN1) {
          size_t o = (size_t)m * MLP + n;
          __half2 p = __floats2half2_rn(gelu_f(v0), gelu_f(v1));
          *(uint32_t*)(g_m1 + o) = *reinterpret_cast<uint32_t*>(&p);
        } else {
          size_t o = (size_t)m * Cc + n;
          float2 r2 = *(const float2*)(g_h + o);
          *(float2*)(outp + o) = make_float2(r2.x + v0, r2.y + v1);
        }
      }
    }
  }
}

// ===== flash attention: augmented QK, one CTA per (win,head), 13 warps =====
__global__ __launch_bounds__(ATH) void k_attn(const float* __restrict__ rph,
                                              const float* __restrict__ rpw) {
  extern __shared__ __align__(128) char asm_[];
  const int hb = blockIdx.x;
  const int win = hb / NH, head = hb - win * NH;
  const int tid = threadIdx.x;
  const int wid = tid >> 5, lane = tid & 31;
  const uint32_t smb = s2u(asm_);

  const __half* qg = g_q + (size_t)hb * NTOK * HD;
  const __half* kg = g_k + (size_t)hb * NTOK * HD;
  const __half* vg = g_v + (size_t)hb * NTOK * HD;

  // ---- phase 1: loads + zeroing ----
  for (int i = tid; i < 2 * 28 * 13; i += ATH) {
    int reg = (i < 28 * 13) ? QE_OFF : KE_OFF;
    int ii = (i < 28 * 13) ? i : i - 28 * 13;
    int r = 196 + ii / 13, c = ii % 13;
    *(uint4*)(asm_ + reg + r * QEROW + c * 16) = make_uint4(0, 0, 0, 0);
  }
  for (int i = tid; i < 28 * 9; i += ATH) {
    int r = 196 + i / 9, c = i % 9;
    *(uint4*)(asm_ + V_OFF + r * 144 + c * 16) = make_uint4(0, 0, 0, 0);
  }
  for (int i = tid; i < 196 * 4; i += ATH) {
    int r = i >> 2, c = i & 3;
    *(uint4*)(asm_ + KE_OFF + r * QEROW + 128 + c * 16) = make_uint4(0, 0, 0, 0);
  }
  const __half2 sc2 = __float2half2_rn(0.125f);
  for (int idx = tid; idx < NTOK * 8; idx += ATH) {
    int r = idx >> 3, c = (idx & 7) * 8;
    uint4 v = *(const uint4*)(qg + r * HD + c);
    __half2* pv = (__half2*)&v;
    pv[0] = __hmul2(pv[0], sc2); pv[1] = __hmul2(pv[1], sc2);
    pv[2] = __hmul2(pv[2], sc2); pv[3] = __hmul2(pv[3], sc2);
    *(uint4*)(asm_ + QE_OFF + r * QEROW + c * 2) = v;
    *(uint4*)(asm_ + KE_OFF + r * QEROW + c * 2) = *(const uint4*)(kg + r * HD + c);
    *(uint4*)(asm_ + V_OFF + r * 144 + c * 2) = *(const uint4*)(vg + r * HD + c);
  }
  for (int i = tid; i < 64 * 64; i += ATH) {
    int r = i >> 6, c = i & 63;
    float v = 0.f;
    if (r < 27) v = rph[r * HD + c];
    else if (r < 54) v = rpw[(r - 27) * HD + c];
    *(__half*)(asm_ + R_OFF + r * 144 + c * 2) = __float2half(v);
  }
  __syncthreads();

  // ---- phase 2: rel-pos table via mma + scatter; K one-hot ----
  const int arow = lane & 15, ahalf = lane >> 4;
  const int bl8 = lane & 7;
  const int bmat = lane >> 3;
  const int bnt_off = (bmat >> 1) * 8;
  const int bhalf = bmat & 1;
  const int er = lane >> 2, ec = (lane & 3) * 2;
  const int mt = wid;  // 0..12
  const int r0 = mt * 16 + er, r1 = r0 + 8;

  uint32_t aq[6][4];
#pragma unroll
  for (int kf = 0; kf < 4; kf++)
    ldsm_x4(aq[kf], smb + QE_OFF + (mt * 16 + arow) * QEROW + kf * 32 + ahalf * 16);

  {
    float t[8][4];
#pragma unroll
    for (int i = 0; i < 8; i++)
#pragma unroll
      for (int q = 0; q < 4; q++) t[i][q] = 0.f;
#pragma unroll
    for (int nt2 = 0; nt2 < 4; nt2++) {
#pragma unroll
      for (int kf = 0; kf < 4; kf++) {
        uint32_t bq[4];
        ldsm_x4(bq, smb + R_OFF + (nt2 * 16 + bnt_off + bl8) * 144 +
                        kf * 32 + bhalf * 16);
        mma_fp16(t[nt2 * 2], aq[kf], bq);
        mma_fp16(t[nt2 * 2 + 1], aq[kf], bq + 2);
      }
    }
    int ih0 = r0 / WS, iw0 = r0 - (r0 / WS) * WS;
    int ih1 = r1 / WS, iw1 = r1 - (r1 / WS) * WS;
#pragma unroll
    for (int nt = 0; nt < 7; nt++) {
#pragma unroll
      for (int q = 0; q < 4; q++) {
        int n = nt * 8 + ec + (q & 1);
        int r = (q < 2) ? r0 : r1;
        if (r >= NTOK) continue;
        int ih = (q < 2) ? ih0 : ih1, iw = (q < 2) ? iw0 : iw1;
        float val = t[nt][q] * 8.f;
        if (n < 27) {
          int kh = ih + 13 - n;
          if ((unsigned)kh < 14u)
            *(__half*)(asm_ + QE_OFF + r * QEROW + (64 + kh) * 2) = __float2half(val);
        } else if (n < 54) {
          int kw = iw + 13 - (n - 27);
          if ((unsigned)kw < 14u)
            *(__half*)(asm_ + QE_OFF + r * QEROW + (78 + kw) * 2) = __float2half(val);
        }
      }
    }
  }
  if (tid < NTOK) {
    int jh = tid / WS, jw = tid - (tid / WS) * WS;
    __half one = __float2half(1.f);
    *(__half*)(asm_ + KE_OFF + tid * QEROW + (64 + jh) * 2) = one;
    *(__half*)(asm_ + KE_OFF + tid * QEROW + (78 + jw) * 2) = one;
  }
  __syncthreads();

#pragma unroll
  for (int kf = 4; kf < 6; kf++)
    ldsm_x4(aq[kf], smb + QE_OFF + (mt * 16 + arow) * QEROW + kf * 32 + ahalf * 16);

  // ---- phase 3: flash mainloop ----
  const int vk = (lane & 7) + ((lane >> 3) & 1) * 8;
  const int vn = (lane >> 4) * 8;

  float m0 = -1e30f, m1 = -1e30f, l0 = 0.f, l1 = 0.f;
  float acc[8][4];
#pragma unroll
  for (int i = 0; i < 8; i++)
#pragma unroll
    for (int q = 0; q < 4; q++) acc[i][q] = 0.f;

#pragma unroll 1
  for (int blk = 0; blk < 4; blk++) {
    const int j0 = blk * 64;
    const int nnt = (blk == 3) ? 2 : 8;
    const int nkf = (blk == 3) ? 1 : 4;
    float s[8][4];
#pragma unroll
    for (int i = 0; i < 8; i++)
#pragma unroll
      for (int q = 0; q < 4; q++) s[i][q] = 0.f;

#pragma unroll
    for (int nt2 = 0; nt2 < 4; nt2++) {
      if (nt2 * 2 >= nnt) break;
#pragma unroll
      for (int kf = 0; kf < 6; kf++) {
        uint32_t bq[4];
        ldsm_x4(bq, smb + KE_OFF + (j0 + nt2 * 16 + bnt_off + bl8) * QEROW +
                        kf * 32 + bhalf * 16);
        mma_fp16(s[nt2 * 2], aq[kf], bq);
        mma_fp16(s[nt2 * 2 + 1], aq[kf], bq + 2);
      }
    }

    if (blk == 3) {
#pragma unroll
      for (int nt = 0; nt < 2; nt++) {
        int jc0 = j0 + nt * 8 + ec, jc1 = jc0 + 1;
        if (jc0 >= NTOK) { s[nt][0] = -1e30f; s[nt][2] = -1e30f; }
        if (jc1 >= NTOK) { s[nt][1] = -1e30f; s[nt][3] = -1e30f; }
      }
    }

    float bm0 = -1e30f, bm1 = -1e30f;
#pragma unroll
    for (int nt = 0; nt < 8; nt++) {
      if (nt >= nnt) break;
      bm0 = fmaxf(bm0, fmaxf(s[nt][0], s[nt][1]));
      bm1 = fmaxf(bm1, fmaxf(s[nt][2], s[nt][3]));
    }
    bm0 = fmaxf(bm0, __shfl_xor_sync(0xffffffffu, bm0, 1));
    bm0 = fmaxf(bm0, __shfl_xor_sync(0xffffffffu, bm0, 2));
    bm1 = fmaxf(bm1, __shfl_xor_sync(0xffffffffu, bm1, 1));
    bm1 = fmaxf(bm1, __shfl_xor_sync(0xffffffffu, bm1, 2));

    float nm0 = fmaxf(m0, bm0), nm1 = fmaxf(m1, bm1);
    float al0 = expf_fast(m0 - nm0), al1 = expf_fast(m1 - nm1);
    m0 = nm0; m1 = nm1;
#pragma unroll
    for (int i = 0; i < 8; i++) {
      acc[i][0] *= al0; acc[i][1] *= al0;
      acc[i][2] *= al1; acc[i][3] *= al1;
    }
    float ps0 = 0.f, ps1 = 0.f;
#pragma unroll
    for (int nt = 0; nt < 8; nt++) {
      if (nt >= nnt) break;
      s[nt][0] = expf_fast(s[nt][0] - nm0);
      s[nt][1] = expf_fast(s[nt][1] - nm0);
      s[nt][2] = expf_fast(s[nt][2] - nm1);
      s[nt][3] = expf_fast(s[nt][3] - nm1);
      ps0 += s[nt][0] + s[nt][1];
      ps1 += s[nt][2] + s[nt][3];
    }
    ps0 += __shfl_xor_sync(0xffffffffu, ps0, 1);
    ps0 += __shfl_xor_sync(0xffffffffu, ps0, 2);
    ps1 += __shfl_xor_sync(0xffffffffu, ps1, 1);
    ps1 += __shfl_xor_sync(0xffffffffu, ps1, 2);
    l0 = l0 * al0 + ps0;
    l1 = l1 * al1 + ps1;

    uint32_t pa[4][4];
#pragma unroll
    for (int kf = 0; kf < 4; kf++) {
      if (kf >= nkf) break;
      __half2 h0 = __floats2half2_rn(s[2 * kf][0], s[2 * kf][1]);
      __half2 h1 = __floats2half2_rn(s[2 * kf][2], s[2 * kf][3]);
      __half2 h2 = __floats2half2_rn(s[2 * kf + 1][0], s[2 * kf + 1][1]);
      __half2 h3 = __floats2half2_rn(s[2 * kf + 1][2], s[2 * kf + 1][3]);
      pa[kf][0] = *reinterpret_cast<uint32_t*>(&h0);
      pa[kf][1] = *reinterpret_cast<uint32_t*>(&h1);
      pa[kf][2] = *reinterpret_cast<uint32_t*>(&h2);
      pa[kf][3] = *reinterpret_cast<uint32_t*>(&h3);
    }

#pragma unroll
    for (int dp = 0; dp < 4; dp++) {
#pragma unroll
      for (int kf = 0; kf < 4; kf++) {
        if (kf >= nkf) break;
        uint32_t bv[4];
        ldsm_x4_t(bv, smb + V_OFF + (j0 + kf * 16 + vk) * 144 +
                          (dp * 16 + vn) * 2);
        mma_fp16(acc[dp * 2], pa[kf], bv);
        mma_fp16(acc[dp * 2 + 1], pa[kf], bv + 2);
      }
    }
  }

  // ---- write output (image layout, skip padded) ----
  float inv0 = 1.f / l0, inv1 = 1.f / l1;
  int bwin = win / 25, wr = win % 25;
  int wh = wr / 5, wwi = wr % 5;
  int i0 = r0 / WS, j0q = r0 - (r0 / WS) * WS;
  int i1 = r1 / WS, j1q = r1 - (r1 / WS) * WS;
  int h0 = wh * WS + i0, w0 = wwi * WS + j0q;
  int h1 = wh * WS + i1, w1 = wwi * WS + j1q;
  bool ok0 = (r0 < NTOK) && (h0 < 64) && (w0 < 64);
  bool ok1 = (r1 < NTOK) && (h1 < 64) && (w1 < 64);
  size_t m0i = (((size_t)bwin * 64 + h0) * 64 + w0) * Cc + head * HD;
  size_t m1i = (((size_t)bwin * 64 + h1) * 64 + w1) * Cc + head * HD;
#pragma unroll
  for (int dt = 0; dt < 8; dt++) {
    int d = dt * 8 + ec;
    if (ok0) {
      __half2 p = __floats2half2_rn(acc[dt][0] * inv0, acc[dt][1] * inv0);
      *(uint32_t*)(g_attn + m0i + d) = *reinterpret_cast<uint32_t*>(&p);
    }
    if (ok1) {
      __half2 p = __floats2half2_rn(acc[dt][2] * inv1, acc[dt][3] * inv1);
      *(uint32_t*)(g_attn + m1i + d) = *reinterpret_cast<uint32_t*>(&p);
    }
  }
}

// ================= launch =================
extern "C" void kernel_launch(void* const* d_in, const int* in_sizes, int n_in,
                              void* d_out, int out_size) {
  (void)in_sizes; (void)n_in; (void)out_size;
  const float* hs    = (const float*)d_in[0];
  const float* ln1g  = (const float*)d_in[1];
  const float* ln1b  = (const float*)d_in[2];
  const float* qkvw  = (const float*)d_in[3];
  const float* qkvb  = (const float*)d_in[4];
  const float* projw = (const float*)d_in[5];
  const float* projb = (const float*)d_in[6];
  const float* rph   = (const float*)d_in[7];
  const float* rpw   = (const float*)d_in[8];
  const float* ln2g  = (const float*)d_in[9];
  const float* ln2b  = (const float*)d_in[10];
  const float* l1w   = (const float*)d_in[11];
  const float* l1b   = (const float*)d_in[12];
  const float* l2w   = (const float*)d_in[13];
  const float* l2b   = (const float*)d_in[14];
  float* out = (float*)d_out;

  cudaFuncSetAttribute(k_attn, cudaFuncAttributeMaxDynamicSharedMemorySize,
                       ATTN_SMEM);
  cudaFuncSetAttribute(k_gemm<EPI_QKV>, cudaFuncAttributeMaxDynamicSharedMemorySize, DYN_SMEM);
  cudaFuncSetAttribute(k_gemm<EPI_PROJ>, cudaFuncAttributeMaxDynamicSharedMemorySize, DYN_SMEM);
  cudaFuncSetAttribute(k_gemm<EPI_LIN1>, cudaFuncAttributeMaxDynamicSharedMemorySize, DYN_SMEM);
  cudaFuncSetAttribute(k_gemm<EPI_LIN2>, cudaFuncAttributeMaxDynamicSharedMemorySize, DYN_SMEM);

  k_wsplit_all<<<6912, 256>>>(qkvw, projw, l1w, l2w);
  k_fillkv<<<NWIN, 256>>>(qkvb);
  k_ln1<<<M2, 256>>>(hs, ln1g, ln1b);

  k_gemm<EPI_QKV><<<dim3(3 * Cc / BN, M2 / BM), 256, DYN_SMEM>>>(
      qkvb, nullptr, nullptr, M2, 3 * Cc, Cc);

  k_attn<<<NWIN * NH, ATH, ATTN_SMEM>>>(rph, rpw);

  k_gemm<EPI_PROJ><<<dim3(Cc / BN, M2 / BM), 256, DYN_SMEM>>>(
      projb, hs, nullptr, M2, Cc, Cc);

  k_ln2<<<M2, 256>>>(ln2g, ln2b);

  k_gemm<EPI_LIN1><<<dim3(MLP / BN, M2 / BM), 256, DYN_SMEM>>>(
      l1b, nullptr, nullptr, M2, MLP, Cc);

  k_gemm<EPI_LIN2><<<dim3(Cc / BN, M2 / BM), 256, DYN_SMEM>>>(
      l2b, nullptr, out, M2, Cc, MLP);
}

// round 14
// speedup vs baseline: 1.0367x; 1.0367x over previous
#include <cuda_runtime.h>
#include <cuda_fp16.h>
#include <math.h>
#include <stdint.h>

// ================= constants =================
namespace {
constexpr int Cc = 768, NH = 12, HD = 64, WS = 14, MLP = 3072;
constexpr int NWIN = 200, NTOK = 196;
constexpr int M2 = 8 * 64 * 64;   // 32768
constexpr float EPS = 1e-6f;

constexpr int BM = 128, BN = 128, BK = 64;
constexpr int ROWB = 144;
constexpr int ARR = BM * ROWB;           // 18432
constexpr int STAGE = 2 * ARR;           // 36864
constexpr int NSTG = 3;
constexpr int DYN_SMEM = NSTG * STAGE;   // 110592 (2 CTA/SM)

// attention smem layout (R10)
constexpr int QEROW = 208;
constexpr int QE_OFF = 0;
constexpr int KE_OFF = 224 * QEROW;
constexpr int V_OFF = KE_OFF + 224 * QEROW;
constexpr int R_OFF = V_OFF + 224 * 144;
constexpr int ATTN_SMEM = R_OFF + 64 * 144;   // 134656
constexpr int ATH = 416;
}

// ================= device scratch =================
__device__ __align__(16) __half g_xln[(size_t)M2 * Cc];
__device__ __align__(16) __half g_q[(size_t)NWIN * NH * NTOK * HD];
__device__ __align__(16) __half g_k[(size_t)NWIN * NH * NTOK * HD];
__device__ __align__(16) __half g_v[(size_t)NWIN * NH * NTOK * HD];
__device__ __align__(16) __half g_attn[(size_t)M2 * Cc];
__device__ __align__(16) float g_h[(size_t)M2 * Cc];
__device__ __align__(16) __half g_x2[(size_t)M2 * Cc];
__device__ __align__(16) __half g_m1[(size_t)M2 * MLP];
__device__ __align__(16) __half g_wq[(size_t)3 * Cc * Cc];
__device__ __align__(16) __half g_wp[(size_t)Cc * Cc];
__device__ __align__(16) __half g_w1[(size_t)MLP * Cc];
__device__ __align__(16) __half g_w2[(size_t)Cc * MLP];

// ================= helpers =================
__device__ __forceinline__ uint32_t s2u(const void* p) {
  uint32_t a;
  asm("{ .reg .u64 t; cvta.to.shared.u64 t, %1; cvt.u32.u64 %0, t; }"
      : "=r"(a) : "l"(p));
  return a;
}
__device__ __forceinline__ void cpa16(uint32_t dst, const void* src, uint32_t sz) {
  asm volatile("cp.async.cg.shared.global [%0], [%1], 16, %2;"
               :: "r"(dst), "l"(src), "r"(sz) : "memory");
}
#define CP_COMMIT() asm volatile("cp.async.commit_group;" ::: "memory")
#define CP_WAIT1() asm volatile("cp.async.wait_group 1;" ::: "memory")

__device__ __forceinline__ void ldsm_x4(uint32_t* r, uint32_t a) {
  asm volatile("ldmatrix.sync.aligned.m8n8.x4.shared.b16 {%0,%1,%2,%3}, [%4];"
               : "=r"(r[0]), "=r"(r[1]), "=r"(r[2]), "=r"(r[3]) : "r"(a));
}
__device__ __forceinline__ void ldsm_x4_t(uint32_t* r, uint32_t a) {
  asm volatile("ldmatrix.sync.aligned.m8n8.x4.trans.shared.b16 {%0,%1,%2,%3}, [%4];"
               : "=r"(r[0]), "=r"(r[1]), "=r"(r[2]), "=r"(r[3]) : "r"(a));
}
__device__ __forceinline__ void mma_fp16(float* d, const uint32_t* a,
                                         const uint32_t* b) {
  asm volatile(
      "mma.sync.aligned.m16n8k16.row.col.f32.f16.f16.f32 "
      "{%0,%1,%2,%3},{%4,%5,%6,%7},{%8,%9},{%0,%1,%2,%3};"
      : "+f"(d[0]), "+f"(d[1]), "+f"(d[2]), "+f"(d[3])
      : "r"(a[0]), "r"(a[1]), "r"(a[2]), "r"(a[3]), "r"(b[0]), "r"(b[1]));
}
__device__ __forceinline__ float expf_fast(float x) {
  float y = fmaxf(x * 1.4426950408889634f, -126.f);
  float t = y + 12582912.f;
  int i = __float_as_int(t) - 0x4B400000;
  float f = y - (t - 12582912.f);
  float p = 0.0013333558f;
  p = fmaf(p, f, 0.0096181291f);
  p = fmaf(p, f, 0.0555041087f);
  p = fmaf(p, f, 0.2402265070f);
  p = fmaf(p, f, 0.6931471806f);
  p = fmaf(p, f, 1.0f);
  return __int_as_float(__float_as_int(p) + (i << 23));
}
__device__ __forceinline__ float rcp_fast(float d) {
  float r = __int_as_float(0x7EF311C3 - __float_as_int(d));
  r = r * fmaf(-d, r, 2.f);
  r = r * fmaf(-d, r, 2.f);
  r = r * fmaf(-d, r, 2.f);
  return r;
}
__device__ __forceinline__ float gelu_f(float x) {
  float z = fabsf(x) * 0.70710678118654752f;
  float t = rcp_fast(fmaf(0.3275911f, z, 1.f));
  float p = 1.061405429f;
  p = fmaf(p, t, -1.453152027f);
  p = fmaf(p, t, 1.421413741f);
  p = fmaf(p, t, -0.284496736f);
  p = fmaf(p, t, 0.254829592f);
  p = p * t;
  float erfz = fmaf(-p, expf_fast(-z * z), 1.f);
  float s = (x >= 0.f) ? erfz : -erfz;
  return 0.5f * x * (1.f + s);
}

// ================= layernorm core =================
__device__ __forceinline__ void ln_compute(const float* __restrict__ xr,
                                           const float* __restrict__ g,
                                           const float* __restrict__ bsh,
                                           __half* __restrict__ o) {
  float vals[3];
  float s = 0.f, s2 = 0.f;
#pragma unroll
  for (int t = 0; t < 3; t++) {
    float v = xr[threadIdx.x + t * 256];
    vals[t] = v; s += v; s2 += v * v;
  }
#pragma unroll
  for (int off = 16; off > 0; off >>= 1) {
    s += __shfl_down_sync(0xffffffffu, s, off);
    s2 += __shfl_down_sync(0xffffffffu, s2, off);
  }
  __shared__ float rs[8], rq[8];
  __shared__ float s_mu, s_inv;
  int lane = threadIdx.x & 31, warp = threadIdx.x >> 5;
  if (lane == 0) { rs[warp] = s; rq[warp] = s2; }
  __syncthreads();
  if (threadIdx.x == 0) {
    float a = 0.f, b2 = 0.f;
#pragma unroll
    for (int i = 0; i < 8; i++) { a += rs[i]; b2 += rq[i]; }
    float mu = a * (1.f / 768.f);
    float var = b2 * (1.f / 768.f) - mu * mu;
    s_mu = mu; s_inv = rsqrtf(var + EPS);
  }
  __syncthreads();
  float mu = s_mu, inv = s_inv;
#pragma unroll
  for (int t = 0; t < 3; t++) {
    int c = threadIdx.x + t * 256;
    o[c] = __float2half((vals[t] - mu) * inv * g[c] + bsh[c]);
  }
}

// ===== merged prologue: wsplit (6912) + fillkv (200) + ln1 (32768) =====
__global__ __launch_bounds__(256) void k_prologue(
    const float* __restrict__ w0, const float* __restrict__ w1,
    const float* __restrict__ w2, const float* __restrict__ w3,
    const float* __restrict__ qkvb, const float* __restrict__ hs,
    const float* __restrict__ ln1g, const float* __restrict__ ln1b) {
  int b = blockIdx.x;
  if (b < 6912) {
    const float* Wsrc;
    __half* T;
    int K, N, nx, ky;
    if (b < 1728) { Wsrc = w0; T = g_wq; K = Cc; N = 3 * Cc; nx = b % 72; ky = b / 72; }
    else if (b < 2304) { b -= 1728; Wsrc = w1; T = g_wp; K = Cc; N = Cc; nx = b % 24; ky = b / 24; }
    else if (b < 4608) { b -= 2304; Wsrc = w2; T = g_w1; K = Cc; N = MLP; nx = b % 96; ky = b / 96; }
    else { b -= 4608; Wsrc = w3; T = g_w2; K = MLP; N = Cc; nx = b % 24; ky = b / 24; }
    __shared__ float t[32][33];
    int n0 = nx * 32, k0 = ky * 32;
    int tx = threadIdx.x & 31, ty = threadIdx.x >> 5;
    for (int r = ty; r < 32; r += 8)
      t[r][tx] = Wsrc[(size_t)(k0 + r) * N + n0 + tx];
    __syncthreads();
    for (int r = ty; r < 32; r += 8)
      T[(size_t)(n0 + r) * K + k0 + tx] = __float2half(t[tx][r]);
  } else if (b < 6912 + NWIN) {
    int win = b - 6912;
    int wr = win % 25;
    int wh = wr / 5, ww = wr % 5;
    if (wh != 4 && ww != 4) return;
    for (int idx = threadIdx.x; idx < NTOK * NH; idx += 256) {
      int tok = idx / NH, head = idx - (idx / NH) * NH;
      int i = tok / WS, j = tok - i * WS;
      int h = wh * WS + i, w = ww * WS + j;
      if (h < 64 && w < 64) continue;
      size_t row = (((size_t)(win * NH + head)) * NTOK + tok) * HD;
      const float* qb = qkvb + head * HD;
      const float* kb = qkvb + Cc + head * HD;
      const float* vb = qkvb + 2 * Cc + head * HD;
#pragma unroll
      for (int d = 0; d < HD; d += 2) {
        __half2 qq = __floats2half2_rn(qb[d], qb[d + 1]);
        __half2 kk = __floats2half2_rn(kb[d], kb[d + 1]);
        __half2 vv = __floats2half2_rn(vb[d], vb[d + 1]);
        *(uint32_t*)(g_q + row + d) = *reinterpret_cast<uint32_t*>(&qq);
        *(uint32_t*)(g_k + row + d) = *reinterpret_cast<uint32_t*>(&kk);
        *(uint32_t*)(g_v + row + d) = *reinterpret_cast<uint32_t*>(&vv);
      }
    }
  } else {
    int m = b - 6912 - NWIN;
    ln_compute(hs + (size_t)m * Cc, ln1g, ln1b, g_xln + (size_t)m * Cc);
  }
}

__global__ __launch_bounds__(256) void k_ln2(const float* __restrict__ g,
                                             const float* __restrict__ b) {
  int m = blockIdx.x;
  ln_compute(g_h + (size_t)m * Cc, g, b, g_x2 + (size_t)m * Cc);
}

// ===== fp16 mma.sync GEMM (EXACT R10: 128x128, 3-stage, 2 CTA/SM) =====
enum { EPI_QKV = 0, EPI_PROJ = 1, EPI_LIN1 = 2, EPI_LIN2 = 3 };

template <int EPI>
__global__ __launch_bounds__(256, 2) void k_gemm(const float* __restrict__ bias,
                                                 const float* __restrict__ extra,
                                                 float* __restrict__ outp,
                                                 int M, int N, int K) {
  extern __shared__ __align__(128) char dsm[];
  const __half *A_g, *B_g;
  if (EPI == EPI_QKV) { A_g = g_xln; B_g = g_wq; }
  else if (EPI == EPI_PROJ) { A_g = g_attn; B_g = g_wp; }
  else if (EPI == EPI_LIN1) { A_g = g_x2; B_g = g_w1; }
  else { A_g = g_m1; B_g = g_w2; }

  const int tid = threadIdx.x;
  const int wid = tid >> 5, lane = tid & 31;
  const int wm = wid >> 2, wn = wid & 3;
  const int row0 = blockIdx.y * BM, col0 = blockIdx.x * BN;
  const uint32_t smb = s2u(dsm);
  const int nch = K / BK;

  const int lr = tid >> 3, lc16 = tid & 7;

  auto load_stage = [&](int c) {
    if (c >= nch) return;
    uint32_t sb = smb + (c % NSTG) * STAGE;
    int k0 = c * BK;
#pragma unroll
    for (int i = 0; i < 4; i++) {
      int r = lr + i * 32;
      uint32_t doff = r * ROWB + lc16 * 16;
      cpa16(sb + doff, A_g + (size_t)(row0 + r) * K + k0 + lc16 * 8, 16u);
      cpa16(sb + ARR + doff, B_g + (size_t)(col0 + r) * K + k0 + lc16 * 8, 16u);
    }
  };

  float acc[4][4][4];
#pragma unroll
  for (int i = 0; i < 4; i++)
#pragma unroll
    for (int j = 0; j < 4; j++)
#pragma unroll
      for (int q = 0; q < 4; q++) acc[i][j][q] = 0.f;

  load_stage(0); CP_COMMIT();
  load_stage(1); CP_COMMIT();

  const int arow = lane & 15, ahalf = lane >> 4;
  const int bl8 = lane & 7;
  const int bmat = lane >> 3;
  const int bnt_off = (bmat >> 1) * 8;
  const int bhalf = bmat & 1;

  for (int c = 0; c < nch; c++) {
    CP_WAIT1();
    __syncthreads();
    uint32_t sb = smb + (c % NSTG) * STAGE;
#pragma unroll
    for (int ks = 0; ks < 4; ks++) {
      uint32_t ah[4][4], bq[2][4];
#pragma unroll
      for (int mt = 0; mt < 4; mt++)
        ldsm_x4(ah[mt],
                sb + (wm * 64 + mt * 16 + arow) * ROWB + ks * 32 + ahalf * 16);
#pragma unroll
      for (int np = 0; np < 2; np++)
        ldsm_x4(bq[np], sb + ARR +
                            (wn * 32 + np * 16 + bnt_off + bl8) * ROWB +
                            ks * 32 + bhalf * 16);
#pragma unroll
      for (int mt = 0; mt < 4; mt++)
#pragma unroll
        for (int nt = 0; nt < 4; nt++)
          mma_fp16(acc[mt][nt], ah[mt], &bq[nt >> 1][(nt & 1) * 2]);
    }
    load_stage(c + 2); CP_COMMIT();
  }

  const int er = lane >> 2, ec = (lane & 3) * 2;
#pragma unroll
  for (int mt = 0; mt < 4; mt++) {
#pragma unroll
    for (int h = 0; h < 2; h++) {
      int m = row0 + wm * 64 + mt * 16 + er + h * 8;
#pragma unroll
      for (int nt = 0; nt < 4; nt++) {
        int n = col0 + wn * 32 + nt * 8 + ec;
        float v0 = acc[mt][nt][2 * h] + bias[n];
        float v1 = acc[mt][nt][2 * h + 1] + bias[n + 1];

        if (EPI == EPI_QKV) {
          int b = m >> 12;
          int rem = m & 4095;
          int hh = rem >> 6, ww2 = rem & 63;
          int wh = (hh * 293) >> 12, ii = hh - wh * WS;
          int wwi = (ww2 * 293) >> 12, jj = ww2 - wwi * WS;
          int win = b * 25 + wh * 5 + wwi;
          int tok = ii * WS + jj;
          int part = n / Cc, cin = n - part * Cc;
          int head = cin >> 6, d = cin & 63;
          __half* dst = (part == 0 ? g_q : part == 1 ? g_k : g_v) +
                        (((size_t)(win * NH + head)) * NTOK + tok) * HD + d;
          __half2 p = __floats2half2_rn(v0, v1);
          *(uint32_t*)dst = *reinterpret_cast<uint32_t*>(&p);
        } else if (EPI == EPI_PROJ) {
          size_t o = (size_t)m * Cc + n;
          float2 r2 = *(const float2*)(extra + o);
          *(float2*)(g_h + o) = make_float2(r2.x + v0, r2.y + v1);
        } else if (EPI == EPI_LIN1) {
          size_t o = (size_t)m * MLP + n;
          __half2 p = __floats2half2_rn(gelu_f(v0), gelu_f(v1));
          *(uint32_t*)(g_m1 + o) = *reinterpret_cast<uint32_t*>(&p);
        } else {
          size_t o = (size_t)m * Cc + n;
          float2 r2 = *(const float2*)(g_h + o);
          *(float2*)(outp + o) = make_float2(r2.x + v0, r2.y + v1);
        }
      }
    }
  }
}

// ===== flash attention (EXACT R10) =====
__global__ __launch_bounds__(ATH) void k_attn(const float* __restrict__ rph,
                                              const float* __restrict__ rpw) {
  extern __shared__ __align__(128) char asm_[];
  const int hb = blockIdx.x;
  const int win = hb / NH, head = hb - win * NH;
  const int tid = threadIdx.x;
  const int wid = tid >> 5, lane = tid & 31;
  const uint32_t smb = s2u(asm_);

  const __half* qg = g_q + (size_t)hb * NTOK * HD;
  const __half* kg = g_k + (size_t)hb * NTOK * HD;
  const __half* vg = g_v + (size_t)hb * NTOK * HD;

  for (int i = tid; i < 2 * 28 * 13; i += ATH) {
    int reg = (i < 28 * 13) ? QE_OFF : KE_OFF;
    int ii = (i < 28 * 13) ? i : i - 28 * 13;
    int r = 196 + ii / 13, c = ii % 13;
    *(uint4*)(asm_ + reg + r * QEROW + c * 16) = make_uint4(0, 0, 0, 0);
  }
  for (int i = tid; i < 28 * 9; i += ATH) {
    int r = 196 + i / 9, c = i % 9;
    *(uint4*)(asm_ + V_OFF + r * 144 + c * 16) = make_uint4(0, 0, 0, 0);
  }
  for (int i = tid; i < 196 * 4; i += ATH) {
    int r = i >> 2, c = i & 3;
    *(uint4*)(asm_ + KE_OFF + r * QEROW + 128 + c * 16) = make_uint4(0, 0, 0, 0);
  }
  const __half2 sc2 = __float2half2_rn(0.125f);
  for (int idx = tid; idx < NTOK * 8; idx += ATH) {
    int r = idx >> 3, c = (idx & 7) * 8;
    uint4 v = *(const uint4*)(qg + r * HD + c);
    __half2* pv = (__half2*)&v;
    pv[0] = __hmul2(pv[0], sc2); pv[1] = __hmul2(pv[1], sc2);
    pv[2] = __hmul2(pv[2], sc2); pv[3] = __hmul2(pv[3], sc2);
    *(uint4*)(asm_ + QE_OFF + r * QEROW + c * 2) = v;
    *(uint4*)(asm_ + KE_OFF + r * QEROW + c * 2) = *(const uint4*)(kg + r * HD + c);
    *(uint4*)(asm_ + V_OFF + r * 144 + c * 2) = *(const uint4*)(vg + r * HD + c);
  }
  for (int i = tid; i < 64 * 64; i += ATH) {
    int r = i >> 6, c = i & 63;
    float v = 0.f;
    if (r < 27) v = rph[r * HD + c];
    else if (r < 54) v = rpw[(r - 27) * HD + c];
    *(__half*)(asm_ + R_OFF + r * 144 + c * 2) = __float2half(v);
  }
  __syncthreads();

  const int arow = lane & 15, ahalf = lane >> 4;
  const int bl8 = lane & 7;
  const int bmat = lane >> 3;
  const int bnt_off = (bmat >> 1) * 8;
  const int bhalf = bmat & 1;
  const int er = lane >> 2, ec = (lane & 3) * 2;
  const int mt = wid;
  const int r0 = mt * 16 + er, r1 = r0 + 8;

  uint32_t aq[6][4];
#pragma unroll
  for (int kf = 0; kf < 4; kf++)
    ldsm_x4(aq[kf], smb + QE_OFF + (mt * 16 + arow) * QEROW + kf * 32 + ahalf * 16);

  {
    float t[8][4];
#pragma unroll
    for (int i = 0; i < 8; i++)
#pragma unroll
      for (int q = 0; q < 4; q++) t[i][q] = 0.f;
#pragma unroll
    for (int nt2 = 0; nt2 < 4; nt2++) {
#pragma unroll
      for (int kf = 0; kf < 4; kf++) {
        uint32_t bq[4];
        ldsm_x4(bq, smb + R_OFF + (nt2 * 16 + bnt_off + bl8) * 144 +
                        kf * 32 + bhalf * 16);
        mma_fp16(t[nt2 * 2], aq[kf], bq);
        mma_fp16(t[nt2 * 2 + 1], aq[kf], bq + 2);
      }
    }
    int ih0 = r0 / WS, iw0 = r0 - (r0 / WS) * WS;
    int ih1 = r1 / WS, iw1 = r1 - (r1 / WS) * WS;
#pragma unroll
    for (int nt = 0; nt < 7; nt++) {
#pragma unroll
      for (int q = 0; q < 4; q++) {
        int n = nt * 8 + ec + (q & 1);
        int r = (q < 2) ? r0 : r1;
        if (r >= NTOK) continue;
        int ih = (q < 2) ? ih0 : ih1, iw = (q < 2) ? iw0 : iw1;
        float val = t[nt][q] * 8.f;
        if (n < 27) {
          int kh = ih + 13 - n;
          if ((unsigned)kh < 14u)
            *(__half*)(asm_ + QE_OFF + r * QEROW + (64 + kh) * 2) = __float2half(val);
        } else if (n < 54) {
          int kw = iw + 13 - (n - 27);
          if ((unsigned)kw < 14u)
            *(__half*)(asm_ + QE_OFF + r * QEROW + (78 + kw) * 2) = __float2half(val);
        }
      }
    }
  }
  if (tid < NTOK) {
    int jh = tid / WS, jw = tid - (tid / WS) * WS;
    __half one = __float2half(1.f);
    *(__half*)(asm_ + KE_OFF + tid * QEROW + (64 + jh) * 2) = one;
    *(__half*)(asm_ + KE_OFF + tid * QEROW + (78 + jw) * 2) = one;
  }
  __syncthreads();

#pragma unroll
  for (int kf = 4; kf < 6; kf++)
    ldsm_x4(aq[kf], smb + QE_OFF + (mt * 16 + arow) * QEROW + kf * 32 + ahalf * 16);

  const int vk = (lane & 7) + ((lane >> 3) & 1) * 8;
  const int vn = (lane >> 4) * 8;

  float m0 = -1e30f, m1 = -1e30f, l0 = 0.f, l1 = 0.f;
  float acc[8][4];
#pragma unroll
  for (int i = 0; i < 8; i++)
#pragma unroll
    for (int q = 0; q < 4; q++) acc[i][q] = 0.f;

#pragma unroll 1
  for (int blk = 0; blk < 4; blk++) {
    const int j0 = blk * 64;
    const int nnt = (blk == 3) ? 2 : 8;
    const int nkf = (blk == 3) ? 1 : 4;
    float s[8][4];
#pragma unroll
    for (int i = 0; i < 8; i++)
#pragma unroll
      for (int q = 0; q < 4; q++) s[i][q] = 0.f;

#pragma unroll
    for (int nt2 = 0; nt2 < 4; nt2++) {
      if (nt2 * 2 >= nnt) break;
#pragma unroll
      for (int kf = 0; kf < 6; kf++) {
        uint32_t bq[4];
        ldsm_x4(bq, smb + KE_OFF + (j0 + nt2 * 16 + bnt_off + bl8) * QEROW +
                        kf * 32 + bhalf * 16);
        mma_fp16(s[nt2 * 2], aq[kf], bq);
        mma_fp16(s[nt2 * 2 + 1], aq[kf], bq + 2);
      }
    }

    if (blk == 3) {
#pragma unroll
      for (int nt = 0; nt < 2; nt++) {
        int jc0 = j0 + nt * 8 + ec, jc1 = jc0 + 1;
        if (jc0 >= NTOK) { s[nt][0] = -1e30f; s[nt][2] = -1e30f; }
        if (jc1 >= NTOK) { s[nt][1] = -1e30f; s[nt][3] = -1e30f; }
      }
    }

    float bm0 = -1e30f, bm1 = -1e30f;
#pragma unroll
    for (int nt = 0; nt < 8; nt++) {
      if (nt >= nnt) break;
      bm0 = fmaxf(bm0, fmaxf(s[nt][0], s[nt][1]));
      bm1 = fmaxf(bm1, fmaxf(s[nt][2], s[nt][3]));
    }
    bm0 = fmaxf(bm0, __shfl_xor_sync(0xffffffffu, bm0, 1));
    bm0 = fmaxf(bm0, __shfl_xor_sync(0xffffffffu, bm0, 2));
    bm1 = fmaxf(bm1, __shfl_xor_sync(0xffffffffu, bm1, 1));
    bm1 = fmaxf(bm1, __shfl_xor_sync(0xffffffffu, bm1, 2));

    float nm0 = fmaxf(m0, bm0), nm1 = fmaxf(m1, bm1);
    float al0 = expf_fast(m0 - nm0), al1 = expf_fast(m1 - nm1);
    m0 = nm0; m1 = nm1;
#pragma unroll
    for (int i = 0; i < 8; i++) {
      acc[i][0] *= al0; acc[i][1] *= al0;
      acc[i][2] *= al1; acc[i][3] *= al1;
    }
    float ps0 = 0.f, ps1 = 0.f;
#pragma unroll
    for (int nt = 0; nt < 8; nt++) {
      if (nt >= nnt) break;
      s[nt][0] = expf_fast(s[nt][0] - nm0);
      s[nt][1] = expf_fast(s[nt][1] - nm0);
      s[nt][2] = expf_fast(s[nt][2] - nm1);
      s[nt][3] = expf_fast(s[nt][3] - nm1);
      ps0 += s[nt][0] + s[nt][1];
      ps1 += s[nt][2] + s[nt][3];
    }
    ps0 += __shfl_xor_sync(0xffffffffu, ps0, 1);
    ps0 += __shfl_xor_sync(0xffffffffu, ps0, 2);
    ps1 += __shfl_xor_sync(0xffffffffu, ps1, 1);
    ps1 += __shfl_xor_sync(0xffffffffu, ps1, 2);
    l0 = l0 * al0 + ps0;
    l1 = l1 * al1 + ps1;

    uint32_t pa[4][4];
#pragma unroll
    for (int kf = 0; kf < 4; kf++) {
      if (kf >= nkf) break;
      __half2 h0 = __floats2half2_rn(s[2 * kf][0], s[2 * kf][1]);
      __half2 h1 = __floats2half2_rn(s[2 * kf][2], s[2 * kf][3]);
      __half2 h2 = __floats2half2_rn(s[2 * kf + 1][0], s[2 * kf + 1][1]);
      __half2 h3 = __floats2half2_rn(s[2 * kf + 1][2], s[2 * kf + 1][3]);
      pa[kf][0] = *reinterpret_cast<uint32_t*>(&h0);
      pa[kf][1] = *reinterpret_cast<uint32_t*>(&h1);
      pa[kf][2] = *reinterpret_cast<uint32_t*>(&h2);
      pa[kf][3] = *reinterpret_cast<uint32_t*>(&h3);
    }

#pragma unroll
    for (int dp = 0; dp < 4; dp++) {
#pragma unroll
      for (int kf = 0; kf < 4; kf++) {
        if (kf >= nkf) break;
        uint32_t bv[4];
        ldsm_x4_t(bv, smb + V_OFF + (j0 + kf * 16 + vk) * 144 +
                          (dp * 16 + vn) * 2);
        mma_fp16(acc[dp * 2], pa[kf], bv);
        mma_fp16(acc[dp * 2 + 1], pa[kf], bv + 2);
      }
    }
  }

  float inv0 = 1.f / l0, inv1 = 1.f / l1;
  int bwin = win / 25, wr = win % 25;
  int wh = wr / 5, wwi = wr % 5;
  int i0 = r0 / WS, j0q = r0 - (r0 / WS) * WS;
  int i1 = r1 / WS, j1q = r1 - (r1 / WS) * WS;
  int h0 = wh * WS + i0, w0 = wwi * WS + j0q;
  int h1 = wh * WS + i1, w1 = wwi * WS + j1q;
  bool ok0 = (r0 < NTOK) && (h0 < 64) && (w0 < 64);
  bool ok1 = (r1 < NTOK) && (h1 < 64) && (w1 < 64);
  size_t m0i = (((size_t)bwin * 64 + h0) * 64 + w0) * Cc + head * HD;
  size_t m1i = (((size_t)bwin * 64 + h1) * 64 + w1) * Cc + head * HD;
#pragma unroll
  for (int dt = 0; dt < 8; dt++) {
    int d = dt * 8 + ec;
    if (ok0) {
      __half2 p = __floats2half2_rn(acc[dt][0] * inv0, acc[dt][1] * inv0);
      *(uint32_t*)(g_attn + m0i + d) = *reinterpret_cast<uint32_t*>(&p);
    }
    if (ok1) {
      __half2 p = __floats2half2_rn(acc[dt][2] * inv1, acc[dt][3] * inv1);
      *(uint32_t*)(g_attn + m1i + d) = *reinterpret_cast<uint32_t*>(&p);
    }
  }
}

// ================= launch =================
extern "C" void kernel_launch(void* const* d_in, const int* in_sizes, int n_in,
                              void* d_out, int out_size) {
  (void)in_sizes; (void)n_in; (void)out_size;
  const float* hs    = (const float*)d_in[0];
  const float* ln1g  = (const float*)d_in[1];
  const float* ln1b  = (const float*)d_in[2];
  const float* qkvw  = (const float*)d_in[3];
  const float* qkvb  = (const float*)d_in[4];
  const float* projw = (const float*)d_in[5];
  const float* projb = (const float*)d_in[6];
  const float* rph   = (const float*)d_in[7];
  const float* rpw   = (const float*)d_in[8];
  const float* ln2g  = (const float*)d_in[9];
  const float* ln2b  = (const float*)d_in[10];
  const float* l1w   = (const float*)d_in[11];
  const float* l1b   = (const float*)d_in[12];
  const float* l2w   = (const float*)d_in[13];
  const float* l2b   = (const float*)d_in[14];
  float* out = (float*)d_out;

  cudaFuncSetAttribute(k_attn, cudaFuncAttributeMaxDynamicSharedMemorySize,
                       ATTN_SMEM);
  cudaFuncSetAttribute(k_gemm<EPI_QKV>, cudaFuncAttributeMaxDynamicSharedMemorySize, DYN_SMEM);
  cudaFuncSetAttribute(k_gemm<EPI_PROJ>, cudaFuncAttributeMaxDynamicSharedMemorySize, DYN_SMEM);
  cudaFuncSetAttribute(k_gemm<EPI_LIN1>, cudaFuncAttributeMaxDynamicSharedMemorySize, DYN_SMEM);
  cudaFuncSetAttribute(k_gemm<EPI_LIN2>, cudaFuncAttributeMaxDynamicSharedMemorySize, DYN_SMEM);

  k_prologue<<<6912 + NWIN + M2, 256>>>(qkvw, projw, l1w, l2w, qkvb, hs,
                                        ln1g, ln1b);

  k_gemm<EPI_QKV><<<dim3(3 * Cc / BN, M2 / BM), 256, DYN_SMEM>>>(
      qkvb, nullptr, nullptr, M2, 3 * Cc, Cc);

  k_attn<<<NWIN * NH, ATH, ATTN_SMEM>>>(rph, rpw);

  k_gemm<EPI_PROJ><<<dim3(Cc / BN, M2 / BM), 256, DYN_SMEM>>>(
      projb, hs, nullptr, M2, Cc, Cc);

  k_ln2<<<M2, 256>>>(ln2g, ln2b);

  k_gemm<EPI_LIN1><<<dim3(MLP / BN, M2 / BM), 256, DYN_SMEM>>>(
      l1b, nullptr, nullptr, M2, MLP, Cc);

  k_gemm<EPI_LIN2><<<dim3(Cc / BN, M2 / BM), 256, DYN_SMEM>>>(
      l2b, nullptr, out, M2, Cc, MLP);
}

// round 15
// speedup vs baseline: 1.0482x; 1.0111x over previous
#include <cuda_runtime.h>
#include <cuda_fp16.h>
#include <math.h>
#include <stdint.h>

// ================= constants =================
namespace {
constexpr int Cc = 768, NH = 12, HD = 64, WS = 14, MLP = 3072;
constexpr int NWIN = 200, NTOK = 196;
constexpr int M2 = 8 * 64 * 64;   // 32768 (image tokens, compact M)
constexpr float EPS = 1e-6f;

constexpr int BM = 128, BN = 128, BK = 64;
constexpr int ROWB = 144;                // 64 fp16 = 128B + 16B pad
constexpr int ARR = BM * ROWB;           // 18432
constexpr int STAGE = 2 * ARR;           // 36864 (A, B)
constexpr int NSTG = 3;
constexpr int DYN_SMEM = NSTG * STAGE;   // 110592 (3 stages, 2 CTA/SM)

// attention smem layout (bytes) — single CTA per (win,head), 13 warps
constexpr int QEROW = 208;                      // 96 halves + 8 pad
constexpr int QE_OFF = 0;                       // 224 x 208
constexpr int KE_OFF = 224 * QEROW;             // 46592
constexpr int V_OFF = KE_OFF + 224 * QEROW;     // 93184 (224 x 144)
constexpr int R_OFF = V_OFF + 224 * 144;        // 125440 (64 x 144)
constexpr int ATTN_SMEM = R_OFF + 64 * 144;     // 134656
constexpr int ATH = 416;                        // 13 warps
}

// ================= device scratch =================
__device__ __align__(16) __half g_xln[(size_t)M2 * Cc];
__device__ __align__(16) __half g_q[(size_t)NWIN * NH * NTOK * HD];
__device__ __align__(16) __half g_k[(size_t)NWIN * NH * NTOK * HD];
__device__ __align__(16) __half g_v[(size_t)NWIN * NH * NTOK * HD];
__device__ __align__(16) __half g_attn[(size_t)M2 * Cc];   // image layout
__device__ __align__(16) float g_h[(size_t)M2 * Cc];
__device__ __align__(16) __half g_x2[(size_t)M2 * Cc];
__device__ __align__(16) __half g_m1[(size_t)M2 * MLP];
__device__ __align__(16) __half g_wq[(size_t)3 * Cc * Cc];
__device__ __align__(16) __half g_wp[(size_t)Cc * Cc];
__device__ __align__(16) __half g_w1[(size_t)MLP * Cc];
__device__ __align__(16) __half g_w2[(size_t)Cc * MLP];

// ================= helpers =================
__device__ __forceinline__ uint32_t s2u(const void* p) {
  uint32_t a;
  asm("{ .reg .u64 t; cvta.to.shared.u64 t, %1; cvt.u32.u64 %0, t; }"
      : "=r"(a) : "l"(p));
  return a;
}
__device__ __forceinline__ void cpa16(uint32_t dst, const void* src, uint32_t sz) {
  asm volatile("cp.async.cg.shared.global [%0], [%1], 16, %2;"
               :: "r"(dst), "l"(src), "r"(sz) : "memory");
}
#define CP_COMMIT() asm volatile("cp.async.commit_group;" ::: "memory")
#define CP_WAIT1() asm volatile("cp.async.wait_group 1;" ::: "memory")

__device__ __forceinline__ void ldsm_x4(uint32_t* r, uint32_t a) {
  asm volatile("ldmatrix.sync.aligned.m8n8.x4.shared.b16 {%0,%1,%2,%3}, [%4];"
               : "=r"(r[0]), "=r"(r[1]), "=r"(r[2]), "=r"(r[3]) : "r"(a));
}
__device__ __forceinline__ void ldsm_x4_t(uint32_t* r, uint32_t a) {
  asm volatile("ldmatrix.sync.aligned.m8n8.x4.trans.shared.b16 {%0,%1,%2,%3}, [%4];"
               : "=r"(r[0]), "=r"(r[1]), "=r"(r[2]), "=r"(r[3]) : "r"(a));
}
__device__ __forceinline__ void mma_fp16(float* d, const uint32_t* a,
                                         const uint32_t* b) {
  asm volatile(
      "mma.sync.aligned.m16n8k16.row.col.f32.f16.f16.f32 "
      "{%0,%1,%2,%3},{%4,%5,%6,%7},{%8,%9},{%0,%1,%2,%3};"
      : "+f"(d[0]), "+f"(d[1]), "+f"(d[2]), "+f"(d[3])
      : "r"(a[0]), "r"(a[1]), "r"(a[2]), "r"(a[3]), "r"(b[0]), "r"(b[1]));
}
__device__ __forceinline__ float expf_fast(float x) {
  float y = fmaxf(x * 1.4426950408889634f, -126.f);
  float t = y + 12582912.f;
  int i = __float_as_int(t) - 0x4B400000;
  float f = y - (t - 12582912.f);
  float p = 0.0013333558f;
  p = fmaf(p, f, 0.0096181291f);
  p = fmaf(p, f, 0.0555041087f);
  p = fmaf(p, f, 0.2402265070f);
  p = fmaf(p, f, 0.6931471806f);
  p = fmaf(p, f, 1.0f);
  return __int_as_float(__float_as_int(p) + (i << 23));
}
__device__ __forceinline__ float rcp_fast(float d) {
  float r = __int_as_float(0x7EF311C3 - __float_as_int(d));
  r = r * fmaf(-d, r, 2.f);
  r = r * fmaf(-d, r, 2.f);
  r = r * fmaf(-d, r, 2.f);
  return r;
}
__device__ __forceinline__ float gelu_f(float x) {
  float z = fabsf(x) * 0.70710678118654752f;
  float t = rcp_fast(fmaf(0.3275911f, z, 1.f));
  float p = 1.061405429f;
  p = fmaf(p, t, -1.453152027f);
  p = fmaf(p, t, 1.421413741f);
  p = fmaf(p, t, -0.284496736f);
  p = fmaf(p, t, 0.254829592f);
  p = p * t;
  float erfz = fmaf(-p, expf_fast(-z * z), 1.f);
  float s = (x >= 0.f) ? erfz : -erfz;
  return 0.5f * x * (1.f + s);
}

// ============ merged weight transpose (fp32 -> fp16 [N][K]) ============
__global__ __launch_bounds__(256) void k_wsplit_all(const float* __restrict__ w0,
                                                    const float* __restrict__ w1,
                                                    const float* __restrict__ w2,
                                                    const float* __restrict__ w3) {
  int b = blockIdx.x;
  const float* Wsrc;
  __half* T;
  int K, N, nx, ky;
  if (b < 1728) { Wsrc = w0; T = g_wq; K = Cc; N = 3 * Cc; nx = b % 72; ky = b / 72; }
  else if (b < 2304) { b -= 1728; Wsrc = w1; T = g_wp; K = Cc; N = Cc; nx = b % 24; ky = b / 24; }
  else if (b < 4608) { b -= 2304; Wsrc = w2; T = g_w1; K = Cc; N = MLP; nx = b % 96; ky = b / 96; }
  else { b -= 4608; Wsrc = w3; T = g_w2; K = MLP; N = Cc; nx = b % 24; ky = b / 24; }
  __shared__ float t[32][33];
  int n0 = nx * 32, k0 = ky * 32;
  int tx = threadIdx.x & 31, ty = threadIdx.x >> 5;
  for (int r = ty; r < 32; r += 8)
    t[r][tx] = Wsrc[(size_t)(k0 + r) * N + n0 + tx];
  __syncthreads();
  for (int r = ty; r < 32; r += 8)
    T[(size_t)(n0 + r) * K + k0 + tx] = __float2half(t[tx][r]);
}

// === fill padded q/k/v slots with bias (padded LN rows are zero rows) ===
__global__ __launch_bounds__(256) void k_fillkv(const float* __restrict__ qkvb) {
  int win = blockIdx.x;
  int wr = win % 25;
  int wh = wr / 5, ww = wr % 5;
  if (wh != 4 && ww != 4) return;
  for (int idx = threadIdx.x; idx < NTOK * NH; idx += 256) {
    int tok = idx / NH, head = idx - (idx / NH) * NH;
    int i = tok / WS, j = tok - i * WS;
    int h = wh * WS + i, w = ww * WS + j;
    if (h < 64 && w < 64) continue;
    size_t row = (((size_t)(win * NH + head)) * NTOK + tok) * HD;
    const float* qb = qkvb + head * HD;
    const float* kb = qkvb + Cc + head * HD;
    const float* vb = qkvb + 2 * Cc + head * HD;
#pragma unroll
    for (int d = 0; d < HD; d += 2) {
      __half2 qq = __floats2half2_rn(qb[d], qb[d + 1]);
      __half2 kk = __floats2half2_rn(kb[d], kb[d + 1]);
      __half2 vv = __floats2half2_rn(vb[d], vb[d + 1]);
      *(uint32_t*)(g_q + row + d) = *reinterpret_cast<uint32_t*>(&qq);
      *(uint32_t*)(g_k + row + d) = *reinterpret_cast<uint32_t*>(&kk);
      *(uint32_t*)(g_v + row + d) = *reinterpret_cast<uint32_t*>(&vv);
    }
  }
}

// ================= layernorm (fp16 out, image layout) =================
__device__ __forceinline__ void ln_compute(const float* __restrict__ xr,
                                           const float* __restrict__ g,
                                           const float* __restrict__ bsh,
                                           __half* __restrict__ o) {
  float vals[3];
  float s = 0.f, s2 = 0.f;
#pragma unroll
  for (int t = 0; t < 3; t++) {
    float v = xr[threadIdx.x + t * 256];
    vals[t] = v; s += v; s2 += v * v;
  }
#pragma unroll
  for (int off = 16; off > 0; off >>= 1) {
    s += __shfl_down_sync(0xffffffffu, s, off);
    s2 += __shfl_down_sync(0xffffffffu, s2, off);
  }
  __shared__ float rs[8], rq[8];
  __shared__ float s_mu, s_inv;
  int lane = threadIdx.x & 31, warp = threadIdx.x >> 5;
  if (lane == 0) { rs[warp] = s; rq[warp] = s2; }
  __syncthreads();
  if (threadIdx.x == 0) {
    float a = 0.f, b2 = 0.f;
#pragma unroll
    for (int i = 0; i < 8; i++) { a += rs[i]; b2 += rq[i]; }
    float mu = a * (1.f / 768.f);
    float var = b2 * (1.f / 768.f) - mu * mu;
    s_mu = mu; s_inv = rsqrtf(var + EPS);
  }
  __syncthreads();
  float mu = s_mu, inv = s_inv;
#pragma unroll
  for (int t = 0; t < 3; t++) {
    int c = threadIdx.x + t * 256;
    o[c] = __float2half((vals[t] - mu) * inv * g[c] + bsh[c]);
  }
}

__global__ __launch_bounds__(256) void k_ln1(const float* __restrict__ x,
                                             const float* __restrict__ g,
                                             const float* __restrict__ b) {
  int m = blockIdx.x;
  ln_compute(x + (size_t)m * Cc, g, b, g_xln + (size_t)m * Cc);
}

__global__ __launch_bounds__(256) void k_ln2(const float* __restrict__ g,
                                             const float* __restrict__ b) {
  int m = blockIdx.x;
  ln_compute(g_h + (size_t)m * Cc, g, b, g_x2 + (size_t)m * Cc);
}

// ============ fp16 mma.sync GEMM (128x128, 3-stage, 2 CTA/SM) ============
enum { EPI_QKV = 0, EPI_PROJ = 1, EPI_LIN1 = 2, EPI_LIN2 = 3 };

template <int EPI>
__global__ __launch_bounds__(256, 2) void k_gemm(const float* __restrict__ bias,
                                                 const float* __restrict__ extra,
                                                 float* __restrict__ outp,
                                                 int M, int N, int K) {
  extern __shared__ __align__(128) char dsm[];
  const __half *A_g, *B_g;
  if (EPI == EPI_QKV) { A_g = g_xln; B_g = g_wq; }
  else if (EPI == EPI_PROJ) { A_g = g_attn; B_g = g_wp; }
  else if (EPI == EPI_LIN1) { A_g = g_x2; B_g = g_w1; }
  else { A_g = g_m1; B_g = g_w2; }

  const int tid = threadIdx.x;
  const int wid = tid >> 5, lane = tid & 31;
  const int wm = wid >> 2, wn = wid & 3;
  const int row0 = blockIdx.y * BM, col0 = blockIdx.x * BN;
  const uint32_t smb = s2u(dsm);
  const int nch = K / BK;

  const int lr = tid >> 3, lc16 = tid & 7;

  auto load_stage = [&](int c) {
    if (c >= nch) return;
    uint32_t sb = smb + (c % NSTG) * STAGE;
    int k0 = c * BK;
#pragma unroll
    for (int i = 0; i < 4; i++) {
      int r = lr + i * 32;
      uint32_t doff = r * ROWB + lc16 * 16;
      cpa16(sb + doff, A_g + (size_t)(row0 + r) * K + k0 + lc16 * 8, 16u);
      cpa16(sb + ARR + doff, B_g + (size_t)(col0 + r) * K + k0 + lc16 * 8, 16u);
    }
  };

  float acc[4][4][4];
#pragma unroll
  for (int i = 0; i < 4; i++)
#pragma unroll
    for (int j = 0; j < 4; j++)
#pragma unroll
      for (int q = 0; q < 4; q++) acc[i][j][q] = 0.f;

  load_stage(0); CP_COMMIT();
  load_stage(1); CP_COMMIT();

  const int arow = lane & 15, ahalf = lane >> 4;
  const int bl8 = lane & 7;
  const int bmat = lane >> 3;
  const int bnt_off = (bmat >> 1) * 8;
  const int bhalf = bmat & 1;

  for (int c = 0; c < nch; c++) {
    CP_WAIT1();
    __syncthreads();
    uint32_t sb = smb + (c % NSTG) * STAGE;
#pragma unroll
    for (int ks = 0; ks < 4; ks++) {
      uint32_t ah[4][4], bq[2][4];
#pragma unroll
      for (int mt = 0; mt < 4; mt++)
        ldsm_x4(ah[mt],
                sb + (wm * 64 + mt * 16 + arow) * ROWB + ks * 32 + ahalf * 16);
#pragma unroll
      for (int np = 0; np < 2; np++)
        ldsm_x4(bq[np], sb + ARR +
                            (wn * 32 + np * 16 + bnt_off + bl8) * ROWB +
                            ks * 32 + bhalf * 16);
#pragma unroll
      for (int mt = 0; mt < 4; mt++)
#pragma unroll
        for (int nt = 0; nt < 4; nt++)
          mma_fp16(acc[mt][nt], ah[mt], &bq[nt >> 1][(nt & 1) * 2]);
    }
    load_stage(c + 2); CP_COMMIT();
  }

  const int er = lane >> 2, ec = (lane & 3) * 2;
#pragma unroll
  for (int mt = 0; mt < 4; mt++) {
#pragma unroll
    for (int h = 0; h < 2; h++) {
      int m = row0 + wm * 64 + mt * 16 + er + h * 8;
#pragma unroll
      for (int nt = 0; nt < 4; nt++) {
        int n = col0 + wn * 32 + nt * 8 + ec;
        float v0 = acc[mt][nt][2 * h] + bias[n];
        float v1 = acc[mt][nt][2 * h + 1] + bias[n + 1];

        if (EPI == EPI_QKV) {
          int b = m >> 12;
          int rem = m & 4095;
          int hh = rem >> 6, ww2 = rem & 63;
          int wh = (hh * 293) >> 12, ii = hh - wh * WS;
          int wwi = (ww2 * 293) >> 12, jj = ww2 - wwi * WS;
          int win = b * 25 + wh * 5 + wwi;
          int tok = ii * WS + jj;
          int part = n / Cc, cin = n - part * Cc;
          int head = cin >> 6, d = cin & 63;
          __half* dst = (part == 0 ? g_q : part == 1 ? g_k : g_v) +
                        (((size_t)(win * NH + head)) * NTOK + tok) * HD + d;
          __half2 p = __floats2half2_rn(v0, v1);
          *(uint32_t*)dst = *reinterpret_cast<uint32_t*>(&p);
        } else if (EPI == EPI_PROJ) {
          size_t o = (size_t)m * Cc + n;
          float2 r2 = *(const float2*)(extra + o);
          *(float2*)(g_h + o) = make_float2(r2.x + v0, r2.y + v1);
        } else if (EPI == EPI_LIN1) {
          size_t o = (size_t)m * MLP + n;
          __half2 p = __floats2half2_rn(gelu_f(v0), gelu_f(v1));
          *(uint32_t*)(g_m1 + o) = *reinterpret_cast<uint32_t*>(&p);
        } else {
          size_t o = (size_t)m * Cc + n;
          float2 r2 = *(const float2*)(g_h + o);
          *(float2*)(outp + o) = make_float2(r2.x + v0, r2.y + v1);
        }
      }
    }
  }
}

// ===== flash attention: augmented QK, one CTA per (win,head), 13 warps =====
__global__ __launch_bounds__(ATH) void k_attn(const float* __restrict__ rph,
                                              const float* __restrict__ rpw) {
  extern __shared__ __align__(128) char asm_[];
  const int hb = blockIdx.x;
  const int win = hb / NH, head = hb - win * NH;
  const int tid = threadIdx.x;
  const int wid = tid >> 5, lane = tid & 31;
  const uint32_t smb = s2u(asm_);

  const __half* qg = g_q + (size_t)hb * NTOK * HD;
  const __half* kg = g_k + (size_t)hb * NTOK * HD;
  const __half* vg = g_v + (size_t)hb * NTOK * HD;

  for (int i = tid; i < 2 * 28 * 13; i += ATH) {
    int reg = (i < 28 * 13) ? QE_OFF : KE_OFF;
    int ii = (i < 28 * 13) ? i : i - 28 * 13;
    int r = 196 + ii / 13, c = ii % 13;
    *(uint4*)(asm_ + reg + r * QEROW + c * 16) = make_uint4(0, 0, 0, 0);
  }
  for (int i = tid; i < 28 * 9; i += ATH) {
    int r = 196 + i / 9, c = i % 9;
    *(uint4*)(asm_ + V_OFF + r * 144 + c * 16) = make_uint4(0, 0, 0, 0);
  }
  for (int i = tid; i < 196 * 4; i += ATH) {
    int r = i >> 2, c = i & 3;
    *(uint4*)(asm_ + KE_OFF + r * QEROW + 128 + c * 16) = make_uint4(0, 0, 0, 0);
  }
  const __half2 sc2 = __float2half2_rn(0.125f);
  for (int idx = tid; idx < NTOK * 8; idx += ATH) {
    int r = idx >> 3, c = (idx & 7) * 8;
    uint4 v = *(const uint4*)(qg + r * HD + c);
    __half2* pv = (__half2*)&v;
    pv[0] = __hmul2(pv[0], sc2); pv[1] = __hmul2(pv[1], sc2);
    pv[2] = __hmul2(pv[2], sc2); pv[3] = __hmul2(pv[3], sc2);
    *(uint4*)(asm_ + QE_OFF + r * QEROW + c * 2) = v;
    *(uint4*)(asm_ + KE_OFF + r * QEROW + c * 2) = *(const uint4*)(kg + r * HD + c);
    *(uint4*)(asm_ + V_OFF + r * 144 + c * 2) = *(const uint4*)(vg + r * HD + c);
  }
  for (int i = tid; i < 64 * 64; i += ATH) {
    int r = i >> 6, c = i & 63;
    float v = 0.f;
    if (r < 27) v = rph[r * HD + c];
    else if (r < 54) v = rpw[(r - 27) * HD + c];
    *(__half*)(asm_ + R_OFF + r * 144 + c * 2) = __float2half(v);
  }
  __syncthreads();

  const int arow = lane & 15, ahalf = lane >> 4;
  const int bl8 = lane & 7;
  const int bmat = lane >> 3;
  const int bnt_off = (bmat >> 1) * 8;
  const int bhalf = bmat & 1;
  const int er = lane >> 2, ec = (lane & 3) * 2;
  const int mt = wid;
  const int r0 = mt * 16 + er, r1 = r0 + 8;

  uint32_t aq[6][4];
#pragma unroll
  for (int kf = 0; kf < 4; kf++)
    ldsm_x4(aq[kf], smb + QE_OFF + (mt * 16 + arow) * QEROW + kf * 32 + ahalf * 16);

  {
    float t[8][4];
#pragma unroll
    for (int i = 0; i < 8; i++)
#pragma unroll
      for (int q = 0; q < 4; q++) t[i][q] = 0.f;
#pragma unroll
    for (int nt2 = 0; nt2 < 4; nt2++) {
#pragma unroll
      for (int kf = 0; kf < 4; kf++) {
        uint32_t bq[4];
        ldsm_x4(bq, smb + R_OFF + (nt2 * 16 + bnt_off + bl8) * 144 +
                        kf * 32 + bhalf * 16);
        mma_fp16(t[nt2 * 2], aq[kf], bq);
        mma_fp16(t[nt2 * 2 + 1], aq[kf], bq + 2);
      }
    }
    int ih0 = r0 / WS, iw0 = r0 - (r0 / WS) * WS;
    int ih1 = r1 / WS, iw1 = r1 - (r1 / WS) * WS;
#pragma unroll
    for (int nt = 0; nt < 7; nt++) {
#pragma unroll
      for (int q = 0; q < 4; q++) {
        int n = nt * 8 + ec + (q & 1);
        int r = (q < 2) ? r0 : r1;
        if (r >= NTOK) continue;
        int ih = (q < 2) ? ih0 : ih1, iw = (q < 2) ? iw0 : iw1;
        float val = t[nt][q] * 8.f;
        if (n < 27) {
          int kh = ih + 13 - n;
          if ((unsigned)kh < 14u)
            *(__half*)(asm_ + QE_OFF + r * QEROW + (64 + kh) * 2) = __float2half(val);
        } else if (n < 54) {
          int kw = iw + 13 - (n - 27);
          if ((unsigned)kw < 14u)
            *(__half*)(asm_ + QE_OFF + r * QEROW + (78 + kw) * 2) = __float2half(val);
        }
      }
    }
  }
  if (tid < NTOK) {
    int jh = tid / WS, jw = tid - (tid / WS) * WS;
    __half one = __float2half(1.f);
    *(__half*)(asm_ + KE_OFF + tid * QEROW + (64 + jh) * 2) = one;
    *(__half*)(asm_ + KE_OFF + tid * QEROW + (78 + jw) * 2) = one;
  }
  __syncthreads();

#pragma unroll
  for (int kf = 4; kf < 6; kf++)
    ldsm_x4(aq[kf], smb + QE_OFF + (mt * 16 + arow) * QEROW + kf * 32 + ahalf * 16);

  const int vk = (lane & 7) + ((lane >> 3) & 1) * 8;
  const int vn = (lane >> 4) * 8;

  float m0 = -1e30f, m1 = -1e30f, l0 = 0.f, l1 = 0.f;
  float acc[8][4];
#pragma unroll
  for (int i = 0; i < 8; i++)
#pragma unroll
    for (int q = 0; q < 4; q++) acc[i][q] = 0.f;

#pragma unroll 1
  for (int blk = 0; blk < 4; blk++) {
    const int j0 = blk * 64;
    const int nnt = (blk == 3) ? 2 : 8;
    const int nkf = (blk == 3) ? 1 : 4;
    float s[8][4];
#pragma unroll
    for (int i = 0; i < 8; i++)
#pragma unroll
      for (int q = 0; q < 4; q++) s[i][q] = 0.f;

#pragma unroll
    for (int nt2 = 0; nt2 < 4; nt2++) {
      if (nt2 * 2 >= nnt) break;
#pragma unroll
      for (int kf = 0; kf < 6; kf++) {
        uint32_t bq[4];
        ldsm_x4(bq, smb + KE_OFF + (j0 + nt2 * 16 + bnt_off + bl8) * QEROW +
                        kf * 32 + bhalf * 16);
        mma_fp16(s[nt2 * 2], aq[kf], bq);
        mma_fp16(s[nt2 * 2 + 1], aq[kf], bq + 2);
      }
    }

    if (blk == 3) {
#pragma unroll
      for (int nt = 0; nt < 2; nt++) {
        int jc0 = j0 + nt * 8 + ec, jc1 = jc0 + 1;
        if (jc0 >= NTOK) { s[nt][0] = -1e30f; s[nt][2] = -1e30f; }
        if (jc1 >= NTOK) { s[nt][1] = -1e30f; s[nt][3] = -1e30f; }
      }
    }

    float bm0 = -1e30f, bm1 = -1e30f;
#pragma unroll
    for (int nt = 0; nt < 8; nt++) {
      if (nt >= nnt) break;
      bm0 = fmaxf(bm0, fmaxf(s[nt][0], s[nt][1]));
      bm1 = fmaxf(bm1, fmaxf(s[nt][2], s[nt][3]));
    }
    bm0 = fmaxf(bm0, __shfl_xor_sync(0xffffffffu, bm0, 1));
    bm0 = fmaxf(bm0, __shfl_xor_sync(0xffffffffu, bm0, 2));
    bm1 = fmaxf(bm1, __shfl_xor_sync(0xffffffffu, bm1, 1));
    bm1 = fmaxf(bm1, __shfl_xor_sync(0xffffffffu, bm1, 2));

    float nm0 = fmaxf(m0, bm0), nm1 = fmaxf(m1, bm1);
    float al0 = expf_fast(m0 - nm0), al1 = expf_fast(m1 - nm1);
    m0 = nm0; m1 = nm1;
#pragma unroll
    for (int i = 0; i < 8; i++) {
      acc[i][0] *= al0; acc[i][1] *= al0;
      acc[i][2] *= al1; acc[i][3] *= al1;
    }
    float ps0 = 0.f, ps1 = 0.f;
#pragma unroll
    for (int nt = 0; nt < 8; nt++) {
      if (nt >= nnt) break;
      s[nt][0] = expf_fast(s[nt][0] - nm0);
      s[nt][1] = expf_fast(s[nt][1] - nm0);
      s[nt][2] = expf_fast(s[nt][2] - nm1);
      s[nt][3] = expf_fast(s[nt][3] - nm1);
      ps0 += s[nt][0] + s[nt][1];
      ps1 += s[nt][2] + s[nt][3];
    }
    ps0 += __shfl_xor_sync(0xffffffffu, ps0, 1);
    ps0 += __shfl_xor_sync(0xffffffffu, ps0, 2);
    ps1 += __shfl_xor_sync(0xffffffffu, ps1, 1);
    ps1 += __shfl_xor_sync(0xffffffffu, ps1, 2);
    l0 = l0 * al0 + ps0;
    l1 = l1 * al1 + ps1;

    uint32_t pa[4][4];
#pragma unroll
    for (int kf = 0; kf < 4; kf++) {
      if (kf >= nkf) break;
      __half2 h0 = __floats2half2_rn(s[2 * kf][0], s[2 * kf][1]);
      __half2 h1 = __floats2half2_rn(s[2 * kf][2], s[2 * kf][3]);
      __half2 h2 = __floats2half2_rn(s[2 * kf + 1][0], s[2 * kf + 1][1]);
      __half2 h3 = __floats2half2_rn(s[2 * kf + 1][2], s[2 * kf + 1][3]);
      pa[kf][0] = *reinterpret_cast<uint32_t*>(&h0);
      pa[kf][1] = *reinterpret_cast<uint32_t*>(&h1);
      pa[kf][2] = *reinterpret_cast<uint32_t*>(&h2);
      pa[kf][3] = *reinterpret_cast<uint32_t*>(&h3);
    }

#pragma unroll
    for (int dp = 0; dp < 4; dp++) {
#pragma unroll
      for (int kf = 0; kf < 4; kf++) {
        if (kf >= nkf) break;
        uint32_t bv[4];
        ldsm_x4_t(bv, smb + V_OFF + (j0 + kf * 16 + vk) * 144 +
                          (dp * 16 + vn) * 2);
        mma_fp16(acc[dp * 2], pa[kf], bv);
        mma_fp16(acc[dp * 2 + 1], pa[kf], bv + 2);
      }
    }
  }

  float inv0 = 1.f / l0, inv1 = 1.f / l1;
  int bwin = win / 25, wr = win % 25;
  int wh = wr / 5, wwi = wr % 5;
  int i0 = r0 / WS, j0q = r0 - (r0 / WS) * WS;
  int i1 = r1 / WS, j1q = r1 - (r1 / WS) * WS;
  int h0 = wh * WS + i0, w0 = wwi * WS + j0q;
  int h1 = wh * WS + i1, w1 = wwi * WS + j1q;
  bool ok0 = (r0 < NTOK) && (h0 < 64) && (w0 < 64);
  bool ok1 = (r1 < NTOK) && (h1 < 64) && (w1 < 64);
  size_t m0i = (((size_t)bwin * 64 + h0) * 64 + w0) * Cc + head * HD;
  size_t m1i = (((size_t)bwin * 64 + h1) * 64 + w1) * Cc + head * HD;
#pragma unroll
  for (int dt = 0; dt < 8; dt++) {
    int d = dt * 8 + ec;
    if (ok0) {
      __half2 p = __floats2half2_rn(acc[dt][0] * inv0, acc[dt][1] * inv0);
      *(uint32_t*)(g_attn + m0i + d) = *reinterpret_cast<uint32_t*>(&p);
    }
    if (ok1) {
      __half2 p = __floats2half2_rn(acc[dt][2] * inv1, acc[dt][3] * inv1);
      *(uint32_t*)(g_attn + m1i + d) = *reinterpret_cast<uint32_t*>(&p);
    }
  }
}

// ================= launch =================
extern "C" void kernel_launch(void* const* d_in, const int* in_sizes, int n_in,
                              void* d_out, int out_size) {
  (void)in_sizes; (void)n_in; (void)out_size;
  const float* hs    = (const float*)d_in[0];
  const float* ln1g  = (const float*)d_in[1];
  const float* ln1b  = (const float*)d_in[2];
  const float* qkvw  = (const float*)d_in[3];
  const float* qkvb  = (const float*)d_in[4];
  const float* projw = (const float*)d_in[5];
  const float* projb = (const float*)d_in[6];
  const float* rph   = (const float*)d_in[7];
  const float* rpw   = (const float*)d_in[8];
  const float* ln2g  = (const float*)d_in[9];
  const float* ln2b  = (const float*)d_in[10];
  const float* l1w   = (const float*)d_in[11];
  const float* l1b   = (const float*)d_in[12];
  const float* l2w   = (const float*)d_in[13];
  const float* l2b   = (const float*)d_in[14];
  float* out = (float*)d_out;

  cudaFuncSetAttribute(k_attn, cudaFuncAttributeMaxDynamicSharedMemorySize,
                       ATTN_SMEM);
  cudaFuncSetAttribute(k_gemm<EPI_QKV>, cudaFuncAttributeMaxDynamicSharedMemorySize, DYN_SMEM);
  cudaFuncSetAttribute(k_gemm<EPI_PROJ>, cudaFuncAttributeMaxDynamicSharedMemorySize, DYN_SMEM);
  cudaFuncSetAttribute(k_gemm<EPI_LIN1>, cudaFuncAttributeMaxDynamicSharedMemorySize, DYN_SMEM);
  cudaFuncSetAttribute(k_gemm<EPI_LIN2>, cudaFuncAttributeMaxDynamicSharedMemorySize, DYN_SMEM);

  k_wsplit_all<<<6912, 256>>>(qkvw, projw, l1w, l2w);
  k_fillkv<<<NWIN, 256>>>(qkvb);
  k_ln1<<<M2, 256>>>(hs, ln1g, ln1b);

  k_gemm<EPI_QKV><<<dim3(3 * Cc / BN, M2 / BM), 256, DYN_SMEM>>>(
      qkvb, nullptr, nullptr, M2, 3 * Cc, Cc);

  k_attn<<<NWIN * NH, ATH, ATTN_SMEM>>>(rph, rpw);

  k_gemm<EPI_PROJ><<<dim3(Cc / BN, M2 / BM), 256, DYN_SMEM>>>(
      projb, hs, nullptr, M2, Cc, Cc);

  k_ln2<<<M2, 256>>>(ln2g, ln2b);

  k_gemm<EPI_LIN1><<<dim3(MLP / BN, M2 / BM), 256, DYN_SMEM>>>(
      l1b, nullptr, nullptr, M2, MLP, Cc);

  k_gemm<EPI_LIN2><<<dim3(Cc / BN, M2 / BM), 256, DYN_SMEM>>>(
      l2b, nullptr, out, M2, Cc, MLP);
}

// round 17
// speedup vs baseline: 1.0721x; 1.0227x over previous
#include <cuda_runtime.h>
#include <cuda_fp16.h>
#include <math.h>
#include <stdint.h>

// ================= constants =================
namespace {
constexpr int Cc = 768, NH = 12, HD = 64, WS = 14, MLP = 3072;
constexpr int NWIN = 200, NTOK = 196;
constexpr int M2 = 8 * 64 * 64;   // 32768 (image tokens, compact M)
constexpr float EPS = 1e-6f;

constexpr int BM = 128, BN = 128, BK = 64;
constexpr int ROWB = 144;                // 64 fp16 = 128B + 16B pad
constexpr int ARR = BM * ROWB;           // 18432
constexpr int STAGE = 2 * ARR;           // 36864 (A, B)
constexpr int NSTG = 3;
constexpr int DYN_SMEM = NSTG * STAGE;   // 110592 (3 stages, 2 CTA/SM)

// attention smem layout (bytes) — single CTA per (win,head), 13 warps
constexpr int QEROW = 208;                      // 96 halves + 8 pad
constexpr int QE_OFF = 0;                       // 224 x 208
constexpr int KE_OFF = 224 * QEROW;             // 46592
constexpr int V_OFF = KE_OFF + 224 * QEROW;     // 93184 (224 x 144)
constexpr int R_OFF = V_OFF + 224 * 144;        // 125440 (64 x 144)
constexpr int ATTN_SMEM = R_OFF + 64 * 144;     // 134656
constexpr int ATH = 416;                        // 13 warps
}

// ================= device scratch =================
__device__ __align__(16) __half g_xln[(size_t)M2 * Cc];
__device__ __align__(16) __half g_q[(size_t)NWIN * NH * NTOK * HD];
__device__ __align__(16) __half g_k[(size_t)NWIN * NH * NTOK * HD];
__device__ __align__(16) __half g_v[(size_t)NWIN * NH * NTOK * HD];
__device__ __align__(16) __half g_attn[(size_t)M2 * Cc];   // image layout
__device__ __align__(16) float g_h[(size_t)M2 * Cc];
__device__ __align__(16) __half g_x2[(size_t)M2 * Cc];
__device__ __align__(16) __half g_m1[(size_t)M2 * MLP];
__device__ __align__(16) __half g_wq[(size_t)3 * Cc * Cc];
__device__ __align__(16) __half g_wp[(size_t)Cc * Cc];
__device__ __align__(16) __half g_w1[(size_t)MLP * Cc];
__device__ __align__(16) __half g_w2[(size_t)Cc * MLP];

// ================= helpers =================
__device__ __forceinline__ uint32_t s2u(const void* p) {
  uint32_t a;
  asm("{ .reg .u64 t; cvta.to.shared.u64 t, %1; cvt.u32.u64 %0, t; }"
      : "=r"(a) : "l"(p));
  return a;
}
__device__ __forceinline__ void cpa16(uint32_t dst, const void* src, uint32_t sz) {
  asm volatile("cp.async.cg.shared.global [%0], [%1], 16, %2;"
               :: "r"(dst), "l"(src), "r"(sz) : "memory");
}
#define CP_COMMIT() asm volatile("cp.async.commit_group;" ::: "memory")
#define CP_WAIT1() asm volatile("cp.async.wait_group 1;" ::: "memory")

__device__ __forceinline__ void ldsm_x4(uint32_t* r, uint32_t a) {
  asm volatile("ldmatrix.sync.aligned.m8n8.x4.shared.b16 {%0,%1,%2,%3}, [%4];"
               : "=r"(r[0]), "=r"(r[1]), "=r"(r[2]), "=r"(r[3]) : "r"(a));
}
__device__ __forceinline__ void ldsm_x4_t(uint32_t* r, uint32_t a) {
  asm volatile("ldmatrix.sync.aligned.m8n8.x4.trans.shared.b16 {%0,%1,%2,%3}, [%4];"
               : "=r"(r[0]), "=r"(r[1]), "=r"(r[2]), "=r"(r[3]) : "r"(a));
}
__device__ __forceinline__ void mma_fp16(float* d, const uint32_t* a,
                                         const uint32_t* b) {
  asm volatile(
      "mma.sync.aligned.m16n8k16.row.col.f32.f16.f16.f32 "
      "{%0,%1,%2,%3},{%4,%5,%6,%7},{%8,%9},{%0,%1,%2,%3};"
      : "+f"(d[0]), "+f"(d[1]), "+f"(d[2]), "+f"(d[3])
      : "r"(a[0]), "r"(a[1]), "r"(a[2]), "r"(a[3]), "r"(b[0]), "r"(b[1]));
}
__device__ __forceinline__ float expf_fast(float x) {
  float y = fmaxf(x * 1.4426950408889634f, -126.f);
  float t = y + 12582912.f;
  int i = __float_as_int(t) - 0x4B400000;
  float f = y - (t - 12582912.f);
  float p = 0.0013333558f;
  p = fmaf(p, f, 0.0096181291f);
  p = fmaf(p, f, 0.0555041087f);
  p = fmaf(p, f, 0.2402265070f);
  p = fmaf(p, f, 0.6931471806f);
  p = fmaf(p, f, 1.0f);
  return __int_as_float(__float_as_int(p) + (i << 23));
}
__device__ __forceinline__ float rcp_fast(float d) {
  float r = __int_as_float(0x7EF311C3 - __float_as_int(d));
  r = r * fmaf(-d, r, 2.f);
  r = r * fmaf(-d, r, 2.f);
  r = r * fmaf(-d, r, 2.f);
  return r;
}
__device__ __forceinline__ float gelu_f(float x) {
  float z = fabsf(x) * 0.70710678118654752f;
  float t = rcp_fast(fmaf(0.3275911f, z, 1.f));
  float p = 1.061405429f;
  p = fmaf(p, t, -1.453152027f);
  p = fmaf(p, t, 1.421413741f);
  p = fmaf(p, t, -0.284496736f);
  p = fmaf(p, t, 0.254829592f);
  p = p * t;
  float erfz = fmaf(-p, expf_fast(-z * z), 1.f);
  float s = (x >= 0.f) ? erfz : -erfz;
  return 0.5f * x * (1.f + s);
}

// ============ merged weight transpose (fp32 -> fp16 [N][K]) ============
__global__ __launch_bounds__(256) void k_wsplit_all(const float* __restrict__ w0,
                                                    const float* __restrict__ w1,
                                                    const float* __restrict__ w2,
                                                    const float* __restrict__ w3) {
  int b = blockIdx.x;
  const float* Wsrc;
  __half* T;
  int K, N, nx, ky;
  if (b < 1728) { Wsrc = w0; T = g_wq; K = Cc; N = 3 * Cc; nx = b % 72; ky = b / 72; }
  else if (b < 2304) { b -= 1728; Wsrc = w1; T = g_wp; K = Cc; N = Cc; nx = b % 24; ky = b / 24; }
  else if (b < 4608) { b -= 2304; Wsrc = w2; T = g_w1; K = Cc; N = MLP; nx = b % 96; ky = b / 96; }
  else { b -= 4608; Wsrc = w3; T = g_w2; K = MLP; N = Cc; nx = b % 24; ky = b / 24; }
  __shared__ float t[32][33];
  int n0 = nx * 32, k0 = ky * 32;
  int tx = threadIdx.x & 31, ty = threadIdx.x >> 5;
  for (int r = ty; r < 32; r += 8)
    t[r][tx] = Wsrc[(size_t)(k0 + r) * N + n0 + tx];
  __syncthreads();
  for (int r = ty; r < 32; r += 8)
    T[(size_t)(n0 + r) * K + k0 + tx] = __float2half(t[tx][r]);
}

// === fill padded q/k/v slots with bias — boundary windows only (72) ===
__global__ __launch_bounds__(256) void k_fillkv(const float* __restrict__ qkvb) {
  int x = blockIdx.x;                 // 0..71
  int bb = x / 9, r = x - bb * 9;
  int wh, ww;
  if (r < 5) { wh = 4; ww = r; }      // bottom row of windows (5)
  else { wh = r - 5; ww = 4; }        // right column, wh 0..3 (4)
  int win = bb * 25 + wh * 5 + ww;
  for (int idx = threadIdx.x; idx < NTOK * NH; idx += 256) {
    int tok = idx / NH, head = idx - (idx / NH) * NH;
    int i = tok / WS, j = tok - i * WS;
    int h = wh * WS + i, w = ww * WS + j;
    if (h < 64 && w < 64) continue;
    size_t row = (((size_t)(win * NH + head)) * NTOK + tok) * HD;
    const float* qb = qkvb + head * HD;
    const float* kb = qkvb + Cc + head * HD;
    const float* vb = qkvb + 2 * Cc + head * HD;
#pragma unroll
    for (int d = 0; d < HD; d += 2) {
      __half2 qq = __floats2half2_rn(qb[d], qb[d + 1]);
      __half2 kk = __floats2half2_rn(kb[d], kb[d + 1]);
      __half2 vv = __floats2half2_rn(vb[d], vb[d + 1]);
      *(uint32_t*)(g_q + row + d) = *reinterpret_cast<uint32_t*>(&qq);
      *(uint32_t*)(g_k + row + d) = *reinterpret_cast<uint32_t*>(&kk);
      *(uint32_t*)(g_v + row + d) = *reinterpret_cast<uint32_t*>(&vv);
    }
  }
}

// ================= layernorm (fp16 out, image layout) =================
__device__ __forceinline__ void ln_compute(const float* __restrict__ xr,
                                           const float* __restrict__ g,
                                           const float* __restrict__ bsh,
                                           __half* __restrict__ o) {
  float vals[3];
  float s = 0.f, s2 = 0.f;
#pragma unroll
  for (int t = 0; t < 3; t++) {
    float v = xr[threadIdx.x + t * 256];
    vals[t] = v; s += v; s2 += v * v;
  }
#pragma unroll
  for (int off = 16; off > 0; off >>= 1) {
    s += __shfl_down_sync(0xffffffffu, s, off);
    s2 += __shfl_down_sync(0xffffffffu, s2, off);
  }
  __shared__ float rs[8], rq[8];
  __shared__ float s_mu, s_inv;
  int lane = threadIdx.x & 31, warp = threadIdx.x >> 5;
  if (lane == 0) { rs[warp] = s; rq[warp] = s2; }
  __syncthreads();
  if (threadIdx.x == 0) {
    float a = 0.f, b2 = 0.f;
#pragma unroll
    for (int i = 0; i < 8; i++) { a += rs[i]; b2 += rq[i]; }
    float mu = a * (1.f / 768.f);
    float var = b2 * (1.f / 768.f) - mu * mu;
    s_mu = mu; s_inv = rsqrtf(var + EPS);
  }
  __syncthreads();
  float mu = s_mu, inv = s_inv;
#pragma unroll
  for (int t = 0; t < 3; t++) {
    int c = threadIdx.x + t * 256;
    o[c] = __float2half((vals[t] - mu) * inv * g[c] + bsh[c]);
  }
}

__global__ __launch_bounds__(256) void k_ln1(const float* __restrict__ x,
                                             const float* __restrict__ g,
                                             const float* __restrict__ b) {
  int m = blockIdx.x;
  ln_compute(x + (size_t)m * Cc, g, b, g_xln + (size_t)m * Cc);
}

__global__ __launch_bounds__(256) void k_ln2(const float* __restrict__ g,
                                             const float* __restrict__ b) {
  int m = blockIdx.x;
  ln_compute(g_h + (size_t)m * Cc, g, b, g_x2 + (size_t)m * Cc);
}

// ============ fp16 mma.sync GEMM (128x128, 3-stage, 2 CTA/SM) ============
enum { EPI_QKV = 0, EPI_PROJ = 1, EPI_LIN1 = 2, EPI_LIN2 = 3 };

template <int EPI>
__global__ __launch_bounds__(256, 2) void k_gemm(const float* __restrict__ bias,
                                                 const float* __restrict__ extra,
                                                 float* __restrict__ outp,
                                                 int M, int N, int K) {
  extern __shared__ __align__(128) char dsm[];
  const __half *A_g, *B_g;
  if (EPI == EPI_QKV) { A_g = g_xln; B_g = g_wq; }
  else if (EPI == EPI_PROJ) { A_g = g_attn; B_g = g_wp; }
  else if (EPI == EPI_LIN1) { A_g = g_x2; B_g = g_w1; }
  else { A_g = g_m1; B_g = g_w2; }

  const int tid = threadIdx.x;
  const int wid = tid >> 5, lane = tid & 31;
  const int wm = wid >> 2, wn = wid & 3;
  const int row0 = blockIdx.y * BM, col0 = blockIdx.x * BN;
  const uint32_t smb = s2u(dsm);
  const int nch = K / BK;

  const int lr = tid >> 3, lc16 = tid & 7;

  auto load_stage = [&](int c) {
    if (c >= nch) return;
    uint32_t sb = smb + (c % NSTG) * STAGE;
    int k0 = c * BK;
#pragma unroll
    for (int i = 0; i < 4; i++) {
      int r = lr + i * 32;
      uint32_t doff = r * ROWB + lc16 * 16;
      cpa16(sb + doff, A_g + (size_t)(row0 + r) * K + k0 + lc16 * 8, 16u);
      cpa16(sb + ARR + doff, B_g + (size_t)(col0 + r) * K + k0 + lc16 * 8, 16u);
    }
  };

  float acc[4][4][4];
#pragma unroll
  for (int i = 0; i < 4; i++)
#pragma unroll
    for (int j = 0; j < 4; j++)
#pragma unroll
      for (int q = 0; q < 4; q++) acc[i][j][q] = 0.f;

  load_stage(0); CP_COMMIT();
  load_stage(1); CP_COMMIT();

  const int arow = lane & 15, ahalf = lane >> 4;
  const int bl8 = lane & 7;
  const int bmat = lane >> 3;
  const int bnt_off = (bmat >> 1) * 8;
  const int bhalf = bmat & 1;

  for (int c = 0; c < nch; c++) {
    CP_WAIT1();
    __syncthreads();
    uint32_t sb = smb + (c % NSTG) * STAGE;
#pragma unroll
    for (int ks = 0; ks < 4; ks++) {
      uint32_t ah[4][4], bq[2][4];
#pragma unroll
      for (int mt = 0; mt < 4; mt++)
        ldsm_x4(ah[mt],
                sb + (wm * 64 + mt * 16 + arow) * ROWB + ks * 32 + ahalf * 16);
#pragma unroll
      for (int np = 0; np < 2; np++)
        ldsm_x4(bq[np], sb + ARR +
                            (wn * 32 + np * 16 + bnt_off + bl8) * ROWB +
                            ks * 32 + bhalf * 16);
#pragma unroll
      for (int mt = 0; mt < 4; mt++)
#pragma unroll
        for (int nt = 0; nt < 4; nt++)
          mma_fp16(acc[mt][nt], ah[mt], &bq[nt >> 1][(nt & 1) * 2]);
    }
    load_stage(c + 2); CP_COMMIT();
  }

  const int er = lane >> 2, ec = (lane & 3) * 2;
#pragma unroll
  for (int mt = 0; mt < 4; mt++) {
#pragma unroll
    for (int h = 0; h < 2; h++) {
      int m = row0 + wm * 64 + mt * 16 + er + h * 8;
#pragma unroll
      for (int nt = 0; nt < 4; nt++) {
        int n = col0 + wn * 32 + nt * 8 + ec;
        float v0 = acc[mt][nt][2 * h] + bias[n];
        float v1 = acc[mt][nt][2 * h + 1] + bias[n + 1];

        if (EPI == EPI_QKV) {
          int b = m >> 12;
          int rem = m & 4095;
          int hh = rem >> 6, ww2 = rem & 63;
          int wh = (hh * 293) >> 12, ii = hh - wh * WS;
          int wwi = (ww2 * 293) >> 12, jj = ww2 - wwi * WS;
          int win = b * 25 + wh * 5 + wwi;
          int tok = ii * WS + jj;
          int part = n / Cc, cin = n - part * Cc;
          int head = cin >> 6, d = cin & 63;
          __half* dst = (part == 0 ? g_q : part == 1 ? g_k : g_v) +
                        (((size_t)(win * NH + head)) * NTOK + tok) * HD + d;
          __half2 p = __floats2half2_rn(v0, v1);
          *(uint32_t*)dst = *reinterpret_cast<uint32_t*>(&p);
        } else if (EPI == EPI_PROJ) {
          size_t o = (size_t)m * Cc + n;
          float2 r2 = *(const float2*)(extra + o);
          *(float2*)(g_h + o) = make_float2(r2.x + v0, r2.y + v1);
        } else if (EPI == EPI_LIN1) {
          size_t o = (size_t)m * MLP + n;
          __half2 p = __floats2half2_rn(gelu_f(v0), gelu_f(v1));
          *(uint32_t*)(g_m1 + o) = *reinterpret_cast<uint32_t*>(&p);
        } else {
          size_t o = (size_t)m * Cc + n;
          float2 r2 = *(const float2*)(g_h + o);
          *(float2*)(outp + o) = make_float2(r2.x + v0, r2.y + v1);
        }
      }
    }
  }
}

// ===== flash attention: augmented QK, one CTA per (win,head), 13 warps =====
__global__ __launch_bounds__(ATH) void k_attn(const float* __restrict__ rph,
                                              const float* __restrict__ rpw) {
  extern __shared__ __align__(128) char asm_[];
  const int hb = blockIdx.x;
  const int win = hb / NH, head = hb - win * NH;
  const int tid = threadIdx.x;
  const int wid = tid >> 5, lane = tid & 31;
  const uint32_t smb = s2u(asm_);

  const __half* qg = g_q + (size_t)hb * NTOK * HD;
  const __half* kg = g_k + (size_t)hb * NTOK * HD;
  const __half* vg = g_v + (size_t)hb * NTOK * HD;

  for (int i = tid; i < 2 * 28 * 13; i += ATH) {
    int reg = (i < 28 * 13) ? QE_OFF : KE_OFF;
    int ii = (i < 28 * 13) ? i : i - 28 * 13;
    int r = 196 + ii / 13, c = ii % 13;
    *(uint4*)(asm_ + reg + r * QEROW + c * 16) = make_uint4(0, 0, 0, 0);
  }
  for (int i = tid; i < 28 * 9; i += ATH) {
    int r = 196 + i / 9, c = i % 9;
    *(uint4*)(asm_ + V_OFF + r * 144 + c * 16) = make_uint4(0, 0, 0, 0);
  }
  for (int i = tid; i < 196 * 4; i += ATH) {
    int r = i >> 2, c = i & 3;
    *(uint4*)(asm_ + KE_OFF + r * QEROW + 128 + c * 16) = make_uint4(0, 0, 0, 0);
  }
  const __half2 sc2 = __float2half2_rn(0.125f);
  for (int idx = tid; idx < NTOK * 8; idx += ATH) {
    int r = idx >> 3, c = (idx & 7) * 8;
    uint4 v = *(const uint4*)(qg + r * HD + c);
    __half2* pv = (__half2*)&v;
    pv[0] = __hmul2(pv[0], sc2); pv[1] = __hmul2(pv[1], sc2);
    pv[2] = __hmul2(pv[2], sc2); pv[3] = __hmul2(pv[3], sc2);
    *(uint4*)(asm_ + QE_OFF + r * QEROW + c * 2) = v;
    *(uint4*)(asm_ + KE_OFF + r * QEROW + c * 2) = *(const uint4*)(kg + r * HD + c);
    *(uint4*)(asm_ + V_OFF + r * 144 + c * 2) = *(const uint4*)(vg + r * HD + c);
  }
  for (int i = tid; i < 64 * 64; i += ATH) {
    int r = i >> 6, c = i & 63;
    float v = 0.f;
    if (r < 27) v = rph[r * HD + c];
    else if (r < 54) v = rpw[(r - 27) * HD + c];
    *(__half*)(asm_ + R_OFF + r * 144 + c * 2) = __float2half(v);
  }
  __syncthreads();

  const int arow = lane & 15, ahalf = lane >> 4;
  const int bl8 = lane & 7;
  const int bmat = lane >> 3;
  const int bnt_off = (bmat >> 1) * 8;
  const int bhalf = bmat & 1;
  const int er = lane >> 2, ec = (lane & 3) * 2;
  const int mt = wid;
  const int r0 = mt * 16 + er, r1 = r0 + 8;

  uint32_t aq[6][4];
#pragma unroll
  for (int kf = 0; kf < 4; kf++)
    ldsm_x4(aq[kf], smb + QE_OFF + (mt * 16 + arow) * QEROW + kf * 32 + ahalf * 16);

  {
    float t[8][4];
#pragma unroll
    for (int i = 0; i < 8; i++)
#pragma unroll
      for (int q = 0; q < 4; q++) t[i][q] = 0.f;
#pragma unroll
    for (int nt2 = 0; nt2 < 4; nt2++) {
#pragma unroll
      for (int kf = 0; kf < 4; kf++) {
        uint32_t bq[4];
        ldsm_x4(bq, smb + R_OFF + (nt2 * 16 + bnt_off + bl8) * 144 +
                        kf * 32 + bhalf * 16);
        mma_fp16(t[nt2 * 2], aq[kf], bq);
        mma_fp16(t[nt2 * 2 + 1], aq[kf], bq + 2);
      }
    }
    int ih0 = r0 / WS, iw0 = r0 - (r0 / WS) * WS;
    int ih1 = r1 / WS, iw1 = r1 - (r1 / WS) * WS;
#pragma unroll
    for (int nt = 0; nt < 7; nt++) {
#pragma unroll
      for (int q = 0; q < 4; q++) {
        int n = nt * 8 + ec + (q & 1);
        int r = (q < 2) ? r0 : r1;
        if (r >= NTOK) continue;
        int ih = (q < 2) ? ih0 : ih1, iw = (q < 2) ? iw0 : iw1;
        float val = t[nt][q] * 8.f;
        if (n < 27) {
          int kh = ih + 13 - n;
          if ((unsigned)kh < 14u)
            *(__half*)(asm_ + QE_OFF + r * QEROW + (64 + kh) * 2) = __float2half(val);
        } else if (n < 54) {
          int kw = iw + 13 - (n - 27);
          if ((unsigned)kw < 14u)
            *(__half*)(asm_ + QE_OFF + r * QEROW + (78 + kw) * 2) = __float2half(val);
        }
      }
    }
  }
  if (tid < NTOK) {
    int jh = tid / WS, jw = tid - (tid / WS) * WS;
    __half one = __float2half(1.f);
    *(__half*)(asm_ + KE_OFF + tid * QEROW + (64 + jh) * 2) = one;
    *(__half*)(asm_ + KE_OFF + tid * QEROW + (78 + jw) * 2) = one;
  }
  __syncthreads();

#pragma unroll
  for (int kf = 4; kf < 6; kf++)
    ldsm_x4(aq[kf], smb + QE_OFF + (mt * 16 + arow) * QEROW + kf * 32 + ahalf * 16);

  const int vk = (lane & 7) + ((lane >> 3) & 1) * 8;
  const int vn = (lane >> 4) * 8;

  float m0 = -1e30f, m1 = -1e30f, l0 = 0.f, l1 = 0.f;
  float acc[8][4];
#pragma unroll
  for (int i = 0; i < 8; i++)
#pragma unroll
    for (int q = 0; q < 4; q++) acc[i][q] = 0.f;

#pragma unroll 1
  for (int blk = 0; blk < 4; blk++) {
    const int j0 = blk * 64;
    const int nnt = (blk == 3) ? 2 : 8;
    const int nkf = (blk == 3) ? 1 : 4;
    float s[8][4];
#pragma unroll
    for (int i = 0; i < 8; i++)
#pragma unroll
      for (int q = 0; q < 4; q++) s[i][q] = 0.f;

#pragma unroll
    for (int nt2 = 0; nt2 < 4; nt2++) {
      if (nt2 * 2 >= nnt) break;
#pragma unroll
      for (int kf = 0; kf < 6; kf++) {
        uint32_t bq[4];
        ldsm_x4(bq, smb + KE_OFF + (j0 + nt2 * 16 + bnt_off + bl8) * QEROW +
                        kf * 32 + bhalf * 16);
        mma_fp16(s[nt2 * 2], aq[kf], bq);
        mma_fp16(s[nt2 * 2 + 1], aq[kf], bq + 2);
      }
    }

    if (blk == 3) {
#pragma unroll
      for (int nt = 0; nt < 2; nt++) {
        int jc0 = j0 + nt * 8 + ec, jc1 = jc0 + 1;
        if (jc0 >= NTOK) { s[nt][0] = -1e30f; s[nt][2] = -1e30f; }
        if (jc1 >= NTOK) { s[nt][1] = -1e30f; s[nt][3] = -1e30f; }
      }
    }

    float bm0 = -1e30f, bm1 = -1e30f;
#pragma unroll
    for (int nt = 0; nt < 8; nt++) {
      if (nt >= nnt) break;
      bm0 = fmaxf(bm0, fmaxf(s[nt][0], s[nt][1]));
      bm1 = fmaxf(bm1, fmaxf(s[nt][2], s[nt][3]));
    }
    bm0 = fmaxf(bm0, __shfl_xor_sync(0xffffffffu, bm0, 1));
    bm0 = fmaxf(bm0, __shfl_xor_sync(0xffffffffu, bm0, 2));
    bm1 = fmaxf(bm1, __shfl_xor_sync(0xffffffffu, bm1, 1));
    bm1 = fmaxf(bm1, __shfl_xor_sync(0xffffffffu, bm1, 2));

    float nm0 = fmaxf(m0, bm0), nm1 = fmaxf(m1, bm1);
    float al0 = expf_fast(m0 - nm0), al1 = expf_fast(m1 - nm1);
    m0 = nm0; m1 = nm1;
#pragma unroll
    for (int i = 0; i < 8; i++) {
      acc[i][0] *= al0; acc[i][1] *= al0;
      acc[i][2] *= al1; acc[i][3] *= al1;
    }
    float ps0 = 0.f, ps1 = 0.f;
#pragma unroll
    for (int nt = 0; nt < 8; nt++) {
      if (nt >= nnt) break;
      s[nt][0] = expf_fast(s[nt][0] - nm0);
      s[nt][1] = expf_fast(s[nt][1] - nm0);
      s[nt][2] = expf_fast(s[nt][2] - nm1);
      s[nt][3] = expf_fast(s[nt][3] - nm1);
      ps0 += s[nt][0] + s[nt][1];
      ps1 += s[nt][2] + s[nt][3];
    }
    ps0 += __shfl_xor_sync(0xffffffffu, ps0, 1);
    ps0 += __shfl_xor_sync(0xffffffffu, ps0, 2);
    ps1 += __shfl_xor_sync(0xffffffffu, ps1, 1);
    ps1 += __shfl_xor_sync(0xffffffffu, ps1, 2);
    l0 = l0 * al0 + ps0;
    l1 = l1 * al1 + ps1;

    uint32_t pa[4][4];
#pragma unroll
    for (int kf = 0; kf < 4; kf++) {
      if (kf >= nkf) break;
      __half2 h0 = __floats2half2_rn(s[2 * kf][0], s[2 * kf][1]);
      __half2 h1 = __floats2half2_rn(s[2 * kf][2], s[2 * kf][3]);
      __half2 h2 = __floats2half2_rn(s[2 * kf + 1][0], s[2 * kf + 1][1]);
      __half2 h3 = __floats2half2_rn(s[2 * kf + 1][2], s[2 * kf + 1][3]);
      pa[kf][0] = *reinterpret_cast<uint32_t*>(&h0);
      pa[kf][1] = *reinterpret_cast<uint32_t*>(&h1);
      pa[kf][2] = *reinterpret_cast<uint32_t*>(&h2);
      pa[kf][3] = *reinterpret_cast<uint32_t*>(&h3);
    }

#pragma unroll
    for (int dp = 0; dp < 4; dp++) {
#pragma unroll
      for (int kf = 0; kf < 4; kf++) {
        if (kf >= nkf) break;
        uint32_t bv[4];
        ldsm_x4_t(bv, smb + V_OFF + (j0 + kf * 16 + vk) * 144 +
                          (dp * 16 + vn) * 2);
        mma_fp16(acc[dp * 2], pa[kf], bv);
        mma_fp16(acc[dp * 2 + 1], pa[kf], bv + 2);
      }
    }
  }

  float inv0 = 1.f / l0, inv1 = 1.f / l1;
  int bwin = win / 25, wr = win % 25;
  int wh = wr / 5, wwi = wr % 5;
  int i0 = r0 / WS, j0q = r0 - (r0 / WS) * WS;
  int i1 = r1 / WS, j1q = r1 - (r1 / WS) * WS;
  int h0 = wh * WS + i0, w0 = wwi * WS + j0q;
  int h1 = wh * WS + i1, w1 = wwi * WS + j1q;
  bool ok0 = (r0 < NTOK) && (h0 < 64) && (w0 < 64);
  bool ok1 = (r1 < NTOK) && (h1 < 64) && (w1 < 64);
  size_t m0i = (((size_t)bwin * 64 + h0) * 64 + w0) * Cc + head * HD;
  size_t m1i = (((size_t)bwin * 64 + h1) * 64 + w1) * Cc + head * HD;
#pragma unroll
  for (int dt = 0; dt < 8; dt++) {
    int d = dt * 8 + ec;
    if (ok0) {
      __half2 p = __floats2half2_rn(acc[dt][0] * inv0, acc[dt][1] * inv0);
      *(uint32_t*)(g_attn + m0i + d) = *reinterpret_cast<uint32_t*>(&p);
    }
    if (ok1) {
      __half2 p = __floats2half2_rn(acc[dt][2] * inv1, acc[dt][3] * inv1);
      *(uint32_t*)(g_attn + m1i + d) = *reinterpret_cast<uint32_t*>(&p);
    }
  }
}

// ================= launch =================
extern "C" void kernel_launch(void* const* d_in, const int* in_sizes, int n_in,
                              void* d_out, int out_size) {
  (void)in_sizes; (void)n_in; (void)out_size;
  const float* hs    = (const float*)d_in[0];
  const float* ln1g  = (const float*)d_in[1];
  const float* ln1b  = (const float*)d_in[2];
  const float* qkvw  = (const float*)d_in[3];
  const float* qkvb  = (const float*)d_in[4];
  const float* projw = (const float*)d_in[5];
  const float* projb = (const float*)d_in[6];
  const float* rph   = (const float*)d_in[7];
  const float* rpw   = (const float*)d_in[8];
  const float* ln2g  = (const float*)d_in[9];
  const float* ln2b  = (const float*)d_in[10];
  const float* l1w   = (const float*)d_in[11];
  const float* l1b   = (const float*)d_in[12];
  const float* l2w   = (const float*)d_in[13];
  const float* l2b   = (const float*)d_in[14];
  float* out = (float*)d_out;

  cudaFuncSetAttribute(k_attn, cudaFuncAttributeMaxDynamicSharedMemorySize,
                       ATTN_SMEM);
  cudaFuncSetAttribute(k_gemm<EPI_QKV>, cudaFuncAttributeMaxDynamicSharedMemorySize, DYN_SMEM);
  cudaFuncSetAttribute(k_gemm<EPI_PROJ>, cudaFuncAttributeMaxDynamicSharedMemorySize, DYN_SMEM);
  cudaFuncSetAttribute(k_gemm<EPI_LIN1>, cudaFuncAttributeMaxDynamicSharedMemorySize, DYN_SMEM);
  cudaFuncSetAttribute(k_gemm<EPI_LIN2>, cudaFuncAttributeMaxDynamicSharedMemorySize, DYN_SMEM);

  k_wsplit_all<<<6912, 256>>>(qkvw, projw, l1w, l2w);
  k_fillkv<<<72, 256>>>(qkvb);
  k_ln1<<<M2, 256>>>(hs, ln1g, ln1b);

  k_gemm<EPI_QKV><<<dim3(3 * Cc / BN, M2 / BM), 256, DYN_SMEM>>>(
      qkvb, nullptr, nullptr, M2, 3 * Cc, Cc);

  k_attn<<<NWIN * NH, ATH, ATTN_SMEM>>>(rph, rpw);

  k_gemm<EPI_PROJ><<<dim3(Cc / BN, M2 / BM), 256, DYN_SMEM>>>(
      projb, hs, nullptr, M2, Cc, Cc);

  k_ln2<<<M2, 256>>>(ln2g, ln2b);

  k_gemm<EPI_LIN1><<<dim3(MLP / BN, M2 / BM), 256, DYN_SMEM>>>(
      l1b, nullptr, nullptr, M2, MLP, Cc);

  k_gemm<EPI_LIN2><<<dim3(Cc / BN, M2 / BM), 256, DYN_SMEM>>>(
      l2b, nullptr, out, M2, Cc, MLP);
}